// round 5
// baseline (speedup 1.0000x reference)
#include <cuda_runtime.h>
#include <cuda_bf16.h>
#include <cstdint>

// Problem constants
#define NE 16
#define NH 2048
#define NI 1408
#define NK 2
#define NT 8192
#define CAP (NT * NK)   // 16384 routed slots

// ---------------- scratch (device globals; no cudaMalloc allowed) ----------
__device__ int   g_counts[NE];
__device__ int   g_fill[NE];
__device__ int   g_offsets[NE + 1];
__device__ int   g_slot_token[CAP];
__device__ float g_slot_w[CAP];
__device__ int   g_tok_slot[CAP];     // inverse map: (t,k) -> slot position p
__device__ int   g_is64;

// bf16 split operands (hi + lo), K-major row layouts matching sources
__device__ __align__(16) __nv_bfloat16 g_hid_hi[(size_t)NT * NH];
__device__ __align__(16) __nv_bfloat16 g_hid_lo[(size_t)NT * NH];
__device__ __align__(16) __nv_bfloat16 g_wgu_hi[(size_t)NE * 2 * NI * NH];
__device__ __align__(16) __nv_bfloat16 g_wgu_lo[(size_t)NE * 2 * NI * NH];
__device__ __align__(16) __nv_bfloat16 g_wdn_hi[(size_t)NE * NH * NI];
__device__ __align__(16) __nv_bfloat16 g_wdn_lo[(size_t)NE * NH * NI];
__device__ __align__(16) __nv_bfloat16 g_h_hi[(size_t)CAP * NI];
__device__ __align__(16) __nv_bfloat16 g_h_lo[(size_t)CAP * NI];
// per-slot weighted down-proj output; reduced into d_out at the end
__device__ __align__(16) float g_slot_out[(size_t)CAP * NH];

// ---------------- PTX helpers (baseline ISA only: sm_80+ features) ---------
__device__ __forceinline__ uint32_t smem_u32(const void* p) {
    uint32_t a;
    asm("{ .reg .u64 t; cvta.to.shared.u64 t, %1; cvt.u32.u64 %0, t; }" : "=r"(a) : "l"(p));
    return a;
}
#define CP_ASYNC16(dst, src) \
    asm volatile("cp.async.cg.shared.global [%0], [%1], 16;" :: "r"(dst), "l"(src))
#define CP_COMMIT() asm volatile("cp.async.commit_group;" ::: "memory")
#define CP_WAIT(N)  asm volatile("cp.async.wait_group %0;" :: "n"(N) : "memory")

#define LDSM4(r, addr) \
    asm volatile("ldmatrix.sync.aligned.m8n8.x4.shared.b16 {%0,%1,%2,%3}, [%4];" \
        : "=r"((r)[0]), "=r"((r)[1]), "=r"((r)[2]), "=r"((r)[3]) : "r"(addr))

#define MMA16816(c, a, b0_, b1_) \
    asm volatile("mma.sync.aligned.m16n8k16.row.col.f32.bf16.bf16.f32 " \
        "{%0,%1,%2,%3}, {%4,%5,%6,%7}, {%8,%9}, {%0,%1,%2,%3};" \
        : "+f"((c)[0]), "+f"((c)[1]), "+f"((c)[2]), "+f"((c)[3]) \
        : "r"((a)[0]), "r"((a)[1]), "r"((a)[2]), "r"((a)[3]), "r"(b0_), "r"(b1_))

// ---------------- dtype detection for top_k_index -----------------
__global__ void k_detect(const int* __restrict__ idx32) {
    if (threadIdx.x == 0) {
        int is64 = 1;
        for (int i = 0; i < 256; i++) {
            int lo = idx32[2 * i], hi = idx32[2 * i + 1];
            if (hi != 0 || lo < 0 || lo >= NE) { is64 = 0; break; }
        }
        g_is64 = is64;
    }
}
__device__ __forceinline__ int load_expert(const void* idx, int s) {
    if (g_is64) return (int)((const long long*)idx)[s];
    return ((const int*)idx)[s];
}

// ---------------- routing -----------------
__global__ void k_reset() {
    int i = threadIdx.x;
    if (i < NE) { g_counts[i] = 0; g_fill[i] = 0; }
}
__global__ void k_count(const void* __restrict__ idx) {
    int s = blockIdx.x * blockDim.x + threadIdx.x;
    if (s < CAP) {
        int e = load_expert(idx, s);
        if (e >= 0 && e < NE) atomicAdd(&g_counts[e], 1);
    }
}
__global__ void k_scan() {
    if (threadIdx.x == 0) {
        int acc = 0;
        for (int e = 0; e < NE; e++) { g_offsets[e] = acc; acc += g_counts[e]; }
        g_offsets[NE] = acc;
    }
}
__global__ void k_scatter(const void* __restrict__ idx, const float* __restrict__ w) {
    int s = blockIdx.x * blockDim.x + threadIdx.x;
    if (s < CAP) {
        int e = load_expert(idx, s);
        if (e >= 0 && e < NE) {
            int p = g_offsets[e] + atomicAdd(&g_fill[e], 1);
            g_slot_token[p] = s / NK;
            g_slot_w[p]     = w[s];
            g_tok_slot[s]   = p;
        }
    }
}

// ---------------- fp32 -> bf16 hi/lo split conversions (8 elems/iter) ------
__device__ __forceinline__ void cvt_body(const float4* __restrict__ s,
                                         uint4* __restrict__ hi,
                                         uint4* __restrict__ lo, size_t n8) {
    size_t i = (size_t)blockIdx.x * blockDim.x + threadIdx.x;
    size_t stride = (size_t)gridDim.x * blockDim.x;
    for (; i < n8; i += stride) {
        float4 v0 = s[2 * i], v1 = s[2 * i + 1];
        float f[8] = {v0.x, v0.y, v0.z, v0.w, v1.x, v1.y, v1.z, v1.w};
        __nv_bfloat162 h[4], l[4];
#pragma unroll
        for (int q = 0; q < 4; q++) {
            __nv_bfloat16 a = __float2bfloat16(f[2 * q]);
            __nv_bfloat16 b = __float2bfloat16(f[2 * q + 1]);
            h[q].x = a; h[q].y = b;
            l[q].x = __float2bfloat16(f[2 * q]     - __bfloat162float(a));
            l[q].y = __float2bfloat16(f[2 * q + 1] - __bfloat162float(b));
        }
        hi[i] = *(const uint4*)h;
        lo[i] = *(const uint4*)l;
    }
}
__global__ void k_cvt_hid(const float4* __restrict__ s) {
    cvt_body(s, (uint4*)g_hid_hi, (uint4*)g_hid_lo, (size_t)NT * NH / 8);
}
__global__ void k_cvt_wgu(const float4* __restrict__ s) {
    cvt_body(s, (uint4*)g_wgu_hi, (uint4*)g_wgu_lo, (size_t)NE * 2 * NI * NH / 8);
}
__global__ void k_cvt_wdn(const float4* __restrict__ s) {
    cvt_body(s, (uint4*)g_wdn_hi, (uint4*)g_wdn_lo, (size_t)NE * NH * NI / 8);
}

// ---------------- HMMA GEMMs ----------------
// SMEM per stage: 4 tiles (Ah, Al, Bh, Bl), each 128 rows x 64 bf16 cols with
// stride 72 elems (144 B; row-start banks 0,4,...,28 -> conflict-free ldmatrix).
#define ROW_B   144
#define TILE_BB (128 * ROW_B)         // 18432 B
#define STAGE_B (4 * TILE_BB)         // 73728 B
#define SMEM_TOT (2 * STAGE_B)        // 147456 B

// ---- GEMM1: C[128 slots, 64 gate | 64 up], K = NH, 32 chunks of 64 ----
__global__ __launch_bounds__(256, 1) void k_gemm1() {
    extern __shared__ char smem[];
    const int e     = blockIdx.z;
    const int start = g_offsets[e];
    const int M     = g_offsets[e + 1] - start;
    const int m0    = blockIdx.y * 128;
    if (m0 >= M) return;
    const int i0 = blockIdx.x * 64;     // gridDim.x = NI/64 = 22

    const int tid  = threadIdx.x;
    const int wid  = tid >> 5;
    const int lane = tid & 31;
    uint32_t sb = smem_u32(smem);

    const int vrow = tid >> 3;
    const int col8 = tid & 7;
    size_t arow[4], brow[4];
#pragma unroll
    for (int i = 0; i < 4; i++) {
        int row = vrow + 32 * i;
        int ar  = m0 + row; if (ar >= M) ar = M - 1;
        arow[i] = (size_t)g_slot_token[start + ar] * NH;
        int wr  = (row < 64) ? (i0 + row) : (NI + i0 + row - 64);
        brow[i] = (size_t)e * (2 * NI) * NH + (size_t)wr * NH;
    }

    auto issue = [&](int s, int kk) {
        uint32_t base = sb + s * STAGE_B;
#pragma unroll
        for (int i = 0; i < 4; i++) {
            int row = vrow + 32 * i;
            uint32_t d = base + row * ROW_B + col8 * 16;
            CP_ASYNC16(d + 0 * TILE_BB, g_hid_hi + arow[i] + kk + col8 * 8);
            CP_ASYNC16(d + 1 * TILE_BB, g_hid_lo + arow[i] + kk + col8 * 8);
            CP_ASYNC16(d + 2 * TILE_BB, g_wgu_hi + brow[i] + kk + col8 * 8);
            CP_ASYNC16(d + 3 * TILE_BB, g_wgu_lo + brow[i] + kk + col8 * 8);
        }
    };

    float acc[16][4];
#pragma unroll
    for (int q = 0; q < 16; q++)
#pragma unroll
        for (int i = 0; i < 4; i++) acc[q][i] = 0.f;

    const uint32_t a_off = (uint32_t)((wid * 16 + (lane & 15)) * ROW_B + (lane >> 4) * 16);
    const uint32_t b_off = (uint32_t)(((lane & 7) + ((lane >> 4) & 1) * 8) * ROW_B +
                                      ((lane >> 3) & 1) * 16);

    issue(0, 0);
    CP_COMMIT();

    for (int c = 0; c < NH / 64; c++) {
        if (c + 1 < NH / 64) { issue((c + 1) & 1, (c + 1) * 64); CP_COMMIT(); CP_WAIT(1); }
        else                 { CP_WAIT(0); }
        __syncthreads();
        uint32_t base = sb + (c & 1) * STAGE_B;
#pragma unroll
        for (int kk = 0; kk < 4; kk++) {
            uint32_t ah[4], al[4];
            LDSM4(ah, base + 0 * TILE_BB + a_off + kk * 32);
            LDSM4(al, base + 1 * TILE_BB + a_off + kk * 32);
#pragma unroll
            for (int nt = 0; nt < 8; nt++) {
                uint32_t bh[4], bl[4];
                uint32_t bo = b_off + nt * (16 * ROW_B) + kk * 32;
                LDSM4(bh, base + 2 * TILE_BB + bo);
                LDSM4(bl, base + 3 * TILE_BB + bo);
                MMA16816(acc[2 * nt],     ah, bh[0], bh[1]);
                MMA16816(acc[2 * nt + 1], ah, bh[2], bh[3]);
                MMA16816(acc[2 * nt],     ah, bl[0], bl[1]);
                MMA16816(acc[2 * nt + 1], ah, bl[2], bl[3]);
                MMA16816(acc[2 * nt],     al, bh[0], bh[1]);
                MMA16816(acc[2 * nt + 1], al, bh[2], bh[3]);
            }
        }
        __syncthreads();
    }

    // epilogue: cols 0..63 = gate(i0+j), 64..127 = up(i0+j); h = silu(g)*u
    const int r0 = m0 + wid * 16 + (lane >> 2);
    const int r1 = r0 + 8;
    const int cb = (lane & 3) * 2;
#pragma unroll
    for (int q = 0; q < 8; q++) {
        int col = i0 + q * 8 + cb;
#pragma unroll
        for (int half = 0; half < 2; half++) {
            int row = half ? r1 : r0;
            if (row >= M) continue;
            float g0 = acc[q][2 * half + 0],     g1 = acc[q][2 * half + 1];
            float u0 = acc[q + 8][2 * half + 0], u1 = acc[q + 8][2 * half + 1];
            float h0 = u0 * g0 / (1.f + __expf(-g0));
            float h1 = u1 * g1 / (1.f + __expf(-g1));
            __nv_bfloat16 hh0 = __float2bfloat16(h0), hh1 = __float2bfloat16(h1);
            __nv_bfloat162 ph; ph.x = hh0; ph.y = hh1;
            __nv_bfloat162 pl;
            pl.x = __float2bfloat16(h0 - __bfloat162float(hh0));
            pl.y = __float2bfloat16(h1 - __bfloat162float(hh1));
            size_t o = (size_t)(start + row) * NI + col;
            *(__nv_bfloat162*)(g_h_hi + o) = ph;
            *(__nv_bfloat162*)(g_h_lo + o) = pl;
        }
    }
}

// ---- GEMM2: C[128 slots, 128 hidden], K = NI, 22 chunks of 64.
//      Epilogue: weighted STG into per-slot buffer (no atomics). ----
__global__ __launch_bounds__(256, 1) void k_gemm2() {
    extern __shared__ char smem[];
    const int e     = blockIdx.z;
    const int start = g_offsets[e];
    const int M     = g_offsets[e + 1] - start;
    const int m0    = blockIdx.y * 128;
    if (m0 >= M) return;
    const int n0 = blockIdx.x * 128;    // gridDim.x = NH/128 = 16

    const int tid  = threadIdx.x;
    const int wid  = tid >> 5;
    const int lane = tid & 31;
    uint32_t sb = smem_u32(smem);

    const int vrow = tid >> 3;
    const int col8 = tid & 7;
    size_t arow[4], brow[4];
#pragma unroll
    for (int i = 0; i < 4; i++) {
        int row = vrow + 32 * i;
        int ar  = m0 + row; if (ar >= M) ar = M - 1;
        arow[i] = (size_t)(start + ar) * NI;
        brow[i] = (size_t)e * NH * NI + (size_t)(n0 + row) * NI;
    }

    auto issue = [&](int s, int kk) {
        uint32_t base = sb + s * STAGE_B;
#pragma unroll
        for (int i = 0; i < 4; i++) {
            int row = vrow + 32 * i;
            uint32_t d = base + row * ROW_B + col8 * 16;
            CP_ASYNC16(d + 0 * TILE_BB, g_h_hi   + arow[i] + kk + col8 * 8);
            CP_ASYNC16(d + 1 * TILE_BB, g_h_lo   + arow[i] + kk + col8 * 8);
            CP_ASYNC16(d + 2 * TILE_BB, g_wdn_hi + brow[i] + kk + col8 * 8);
            CP_ASYNC16(d + 3 * TILE_BB, g_wdn_lo + brow[i] + kk + col8 * 8);
        }
    };

    float acc[16][4];
#pragma unroll
    for (int q = 0; q < 16; q++)
#pragma unroll
        for (int i = 0; i < 4; i++) acc[q][i] = 0.f;

    const uint32_t a_off = (uint32_t)((wid * 16 + (lane & 15)) * ROW_B + (lane >> 4) * 16);
    const uint32_t b_off = (uint32_t)(((lane & 7) + ((lane >> 4) & 1) * 8) * ROW_B +
                                      ((lane >> 3) & 1) * 16);

    issue(0, 0);
    CP_COMMIT();

    for (int c = 0; c < NI / 64; c++) {
        if (c + 1 < NI / 64) { issue((c + 1) & 1, (c + 1) * 64); CP_COMMIT(); CP_WAIT(1); }
        else                 { CP_WAIT(0); }
        __syncthreads();
        uint32_t base = sb + (c & 1) * STAGE_B;
#pragma unroll
        for (int kk = 0; kk < 4; kk++) {
            uint32_t ah[4], al[4];
            LDSM4(ah, base + 0 * TILE_BB + a_off + kk * 32);
            LDSM4(al, base + 1 * TILE_BB + a_off + kk * 32);
#pragma unroll
            for (int nt = 0; nt < 8; nt++) {
                uint32_t bh[4], bl[4];
                uint32_t bo = b_off + nt * (16 * ROW_B) + kk * 32;
                LDSM4(bh, base + 2 * TILE_BB + bo);
                LDSM4(bl, base + 3 * TILE_BB + bo);
                MMA16816(acc[2 * nt],     ah, bh[0], bh[1]);
                MMA16816(acc[2 * nt + 1], ah, bh[2], bh[3]);
                MMA16816(acc[2 * nt],     ah, bl[0], bl[1]);
                MMA16816(acc[2 * nt + 1], ah, bl[2], bl[3]);
                MMA16816(acc[2 * nt],     al, bh[0], bh[1]);
                MMA16816(acc[2 * nt + 1], al, bh[2], bh[3]);
            }
        }
        __syncthreads();
    }

    // epilogue: g_slot_out[p, n0+col] = w * acc   (plain stores, no atomics)
    const int r0 = m0 + wid * 16 + (lane >> 2);
    const int cb = (lane & 3) * 2;
#pragma unroll
    for (int half = 0; half < 2; half++) {
        int row = r0 + half * 8;
        if (row >= M) continue;
        float w = g_slot_w[start + row];
        float* brw = g_slot_out + (size_t)(start + row) * NH + n0;
#pragma unroll
        for (int q = 0; q < 16; q++) {
            float2 v;
            v.x = w * acc[q][2 * half + 0];
            v.y = w * acc[q][2 * half + 1];
            *(float2*)(brw + q * 8 + cb) = v;
        }
    }
}

// ---- reduce: out[t] = slot_out[p0(t)] + slot_out[p1(t)] ----
__global__ void k_reduce(float4* __restrict__ out) {
    const int n4 = NT * (NH / 4);
    int idx = blockIdx.x * blockDim.x + threadIdx.x;
    int stride = gridDim.x * blockDim.x;
    const float4* buf = (const float4*)g_slot_out;
    for (; idx < n4; idx += stride) {
        int t  = idx >> 9;                 // NH/4 = 512
        int c4 = idx & 511;
        int p0 = g_tok_slot[2 * t];
        int p1 = g_tok_slot[2 * t + 1];
        float4 a = buf[(size_t)p0 * (NH / 4) + c4];
        float4 b = buf[(size_t)p1 * (NH / 4) + c4];
        float4 r;
        r.x = a.x + b.x; r.y = a.y + b.y; r.z = a.z + b.z; r.w = a.w + b.w;
        out[idx] = r;
    }
}

// ---------------- launch -----------------
extern "C" void kernel_launch(void* const* d_in, const int* in_sizes, int n_in,
                              void* d_out, int out_size) {
    const float* hidden = (const float*)d_in[0];   // [T, H]
    const void*  idx    = d_in[1];                 // [T, K] int32 or int64
    const float* wts    = (const float*)d_in[2];   // [T, K]
    const float* wgu    = (const float*)d_in[3];   // [E, 2I, H]
    const float* wdn    = (const float*)d_in[4];   // [E, H, I]
    (void)in_sizes; (void)n_in; (void)out_size;

    cudaFuncSetAttribute(k_gemm1, cudaFuncAttributeMaxDynamicSharedMemorySize, SMEM_TOT);
    cudaFuncSetAttribute(k_gemm2, cudaFuncAttributeMaxDynamicSharedMemorySize, SMEM_TOT);

    // routing
    k_detect<<<1, 32>>>((const int*)idx);
    k_reset<<<1, 32>>>();
    k_count<<<(CAP + 255) / 256, 256>>>(idx);
    k_scan<<<1, 32>>>();
    k_scatter<<<(CAP + 255) / 256, 256>>>(idx, wts);

    // fp32 -> bf16 hi/lo splits
    k_cvt_hid<<<2048, 256>>>((const float4*)hidden);
    k_cvt_wgu<<<8192, 256>>>((const float4*)wgu);
    k_cvt_wdn<<<4096, 256>>>((const float4*)wdn);

    // GEMM1: x = NI/64 = 22 tiles, y = worst-case M tiles, z = experts
    dim3 g1(NI / 64, CAP / 128, NE);
    k_gemm1<<<g1, 256, SMEM_TOT>>>();

    // GEMM2: x = NH/128 = 16 tiles
    dim3 g2(NH / 128, CAP / 128, NE);
    k_gemm2<<<g2, 256, SMEM_TOT>>>();

    // final combine: out[t] = sum of the token's two expert slots
    k_reduce<<<8192, 256>>>((float4*)d_out);
}

// round 6
// speedup vs baseline: 1.7340x; 1.7340x over previous
#include <cuda_runtime.h>
#include <cuda_bf16.h>
#include <cstdint>

// Problem constants
#define NE 16
#define NH 2048
#define NI 1408
#define NK 2
#define NT 8192
#define CAP (NT * NK)   // 16384 routed slots

// ---------------- scratch (device globals; no cudaMalloc allowed) ----------
__device__ int   g_counts[NE];
__device__ int   g_fill[NE];
__device__ int   g_offsets[NE + 1];
__device__ int   g_slot_token[CAP];
__device__ float g_slot_w[CAP];
__device__ int   g_is64;

// bf16 split operands (hi + lo), K-major row layouts matching sources
__device__ __align__(16) __nv_bfloat16 g_hid_hi[(size_t)NT * NH];
__device__ __align__(16) __nv_bfloat16 g_hid_lo[(size_t)NT * NH];
__device__ __align__(16) __nv_bfloat16 g_wgu_hi[(size_t)NE * 2 * NI * NH];
__device__ __align__(16) __nv_bfloat16 g_wgu_lo[(size_t)NE * 2 * NI * NH];
__device__ __align__(16) __nv_bfloat16 g_wdn_hi[(size_t)NE * NH * NI];
__device__ __align__(16) __nv_bfloat16 g_wdn_lo[(size_t)NE * NH * NI];
__device__ __align__(16) __nv_bfloat16 g_h_hi[(size_t)CAP * NI];
__device__ __align__(16) __nv_bfloat16 g_h_lo[(size_t)CAP * NI];

// ---------------- PTX helpers (baseline ISA only: sm_80+ features) ---------
__device__ __forceinline__ uint32_t smem_u32(const void* p) {
    uint32_t a;
    asm("{ .reg .u64 t; cvta.to.shared.u64 t, %1; cvt.u32.u64 %0, t; }" : "=r"(a) : "l"(p));
    return a;
}
#define CP_ASYNC16(dst, src) \
    asm volatile("cp.async.cg.shared.global [%0], [%1], 16;" :: "r"(dst), "l"(src))
#define CP_COMMIT() asm volatile("cp.async.commit_group;" ::: "memory")
#define CP_WAIT(N)  asm volatile("cp.async.wait_group %0;" :: "n"(N) : "memory")

#define LDSM4(r, addr) \
    asm volatile("ldmatrix.sync.aligned.m8n8.x4.shared.b16 {%0,%1,%2,%3}, [%4];" \
        : "=r"((r)[0]), "=r"((r)[1]), "=r"((r)[2]), "=r"((r)[3]) : "r"(addr))

#define MMA16816(c, a, b0_, b1_) \
    asm volatile("mma.sync.aligned.m16n8k16.row.col.f32.bf16.bf16.f32 " \
        "{%0,%1,%2,%3}, {%4,%5,%6,%7}, {%8,%9}, {%0,%1,%2,%3};" \
        : "+f"((c)[0]), "+f"((c)[1]), "+f"((c)[2]), "+f"((c)[3]) \
        : "r"((a)[0]), "r"((a)[1]), "r"((a)[2]), "r"((a)[3]), "r"(b0_), "r"(b1_))

// ---------------- dtype detection for top_k_index -----------------
__global__ void k_detect(const int* __restrict__ idx32) {
    if (threadIdx.x == 0) {
        int is64 = 1;
        for (int i = 0; i < 256; i++) {
            int lo = idx32[2 * i], hi = idx32[2 * i + 1];
            if (hi != 0 || lo < 0 || lo >= NE) { is64 = 0; break; }
        }
        g_is64 = is64;
    }
}
__device__ __forceinline__ int load_expert(const void* idx, int s) {
    if (g_is64) return (int)((const long long*)idx)[s];
    return ((const int*)idx)[s];
}

// ---------------- routing -----------------
__global__ void k_reset() {
    int i = threadIdx.x;
    if (i < NE) { g_counts[i] = 0; g_fill[i] = 0; }
}
__global__ void k_count(const void* __restrict__ idx) {
    int s = blockIdx.x * blockDim.x + threadIdx.x;
    if (s < CAP) {
        int e = load_expert(idx, s);
        if (e >= 0 && e < NE) atomicAdd(&g_counts[e], 1);
    }
}
__global__ void k_scan() {
    if (threadIdx.x == 0) {
        int acc = 0;
        for (int e = 0; e < NE; e++) { g_offsets[e] = acc; acc += g_counts[e]; }
        g_offsets[NE] = acc;
    }
}
__global__ void k_scatter(const void* __restrict__ idx, const float* __restrict__ w) {
    int s = blockIdx.x * blockDim.x + threadIdx.x;
    if (s < CAP) {
        int e = load_expert(idx, s);
        if (e >= 0 && e < NE) {
            int p = g_offsets[e] + atomicAdd(&g_fill[e], 1);
            g_slot_token[p] = s / NK;
            g_slot_w[p]     = w[s];
        }
    }
}

// ---------------- fp32 -> bf16 hi/lo split conversions ----------------
__device__ __forceinline__ void cvt_body(const float4* __restrict__ s,
                                         __nv_bfloat162* __restrict__ hi,
                                         __nv_bfloat162* __restrict__ lo, size_t n4) {
    size_t i = (size_t)blockIdx.x * blockDim.x + threadIdx.x;
    size_t stride = (size_t)gridDim.x * blockDim.x;
    for (; i < n4; i += stride) {
        float4 v = s[i];
        __nv_bfloat16 hx = __float2bfloat16(v.x), hy = __float2bfloat16(v.y);
        __nv_bfloat16 hz = __float2bfloat16(v.z), hw = __float2bfloat16(v.w);
        __nv_bfloat162 h0; h0.x = hx; h0.y = hy;
        __nv_bfloat162 h1; h1.x = hz; h1.y = hw;
        hi[2 * i]     = h0;
        hi[2 * i + 1] = h1;
        __nv_bfloat162 l0, l1;
        l0.x = __float2bfloat16(v.x - __bfloat162float(hx));
        l0.y = __float2bfloat16(v.y - __bfloat162float(hy));
        l1.x = __float2bfloat16(v.z - __bfloat162float(hz));
        l1.y = __float2bfloat16(v.w - __bfloat162float(hw));
        lo[2 * i]     = l0;
        lo[2 * i + 1] = l1;
    }
}
__global__ void k_cvt_hid(const float4* __restrict__ s) {
    cvt_body(s, (__nv_bfloat162*)g_hid_hi, (__nv_bfloat162*)g_hid_lo, (size_t)NT * NH / 4);
}
__global__ void k_cvt_wgu(const float4* __restrict__ s) {
    cvt_body(s, (__nv_bfloat162*)g_wgu_hi, (__nv_bfloat162*)g_wgu_lo, (size_t)NE * 2 * NI * NH / 4);
}
__global__ void k_cvt_wdn(const float4* __restrict__ s) {
    cvt_body(s, (__nv_bfloat162*)g_wdn_hi, (__nv_bfloat162*)g_wdn_lo, (size_t)NE * NH * NI / 4);
}

// ---------------- HMMA GEMMs ----------------
// SMEM per stage: 4 tiles (Ah, Al, Bh, Bl), each 128 rows x 64 bf16 cols with
// stride 72 elems (144 B; row-start banks 0,4,...,28 -> conflict-free ldmatrix).
// 3-stage cp.async pipeline.
#define ROW_B   144
#define TILE_BB (128 * ROW_B)         // 18432 B
#define STAGE_B (4 * TILE_BB)         // 73728 B
#define NSTAGE  3
#define SMEM_TOT (NSTAGE * STAGE_B)   // 221184 B

// ---- GEMM1: C[128 slots, 64 gate | 64 up], K = NH, 32 chunks of 64 ----
__global__ __launch_bounds__(256, 1) void k_gemm1() {
    extern __shared__ char smem[];
    const int e     = blockIdx.z;
    const int start = g_offsets[e];
    const int M     = g_offsets[e + 1] - start;
    const int m0    = blockIdx.y * 128;
    if (m0 >= M) return;
    const int i0 = blockIdx.x * 64;     // gridDim.x = NI/64 = 22

    const int tid  = threadIdx.x;
    const int wid  = tid >> 5;
    const int lane = tid & 31;
    uint32_t sb = smem_u32(smem);

    const int vrow = tid >> 3;
    const int col8 = tid & 7;
    size_t arow[4], brow[4];
#pragma unroll
    for (int i = 0; i < 4; i++) {
        int row = vrow + 32 * i;
        int ar  = m0 + row; if (ar >= M) ar = M - 1;
        arow[i] = (size_t)g_slot_token[start + ar] * NH;
        int wr  = (row < 64) ? (i0 + row) : (NI + i0 + row - 64);
        brow[i] = (size_t)e * (2 * NI) * NH + (size_t)wr * NH;
    }

    auto issue = [&](int s, int kk) {
        uint32_t base = sb + s * STAGE_B;
#pragma unroll
        for (int i = 0; i < 4; i++) {
            int row = vrow + 32 * i;
            uint32_t d = base + row * ROW_B + col8 * 16;
            CP_ASYNC16(d + 0 * TILE_BB, g_hid_hi + arow[i] + kk + col8 * 8);
            CP_ASYNC16(d + 1 * TILE_BB, g_hid_lo + arow[i] + kk + col8 * 8);
            CP_ASYNC16(d + 2 * TILE_BB, g_wgu_hi + brow[i] + kk + col8 * 8);
            CP_ASYNC16(d + 3 * TILE_BB, g_wgu_lo + brow[i] + kk + col8 * 8);
        }
    };

    float acc[16][4];
#pragma unroll
    for (int q = 0; q < 16; q++)
#pragma unroll
        for (int i = 0; i < 4; i++) acc[q][i] = 0.f;

    const uint32_t a_off = (uint32_t)((wid * 16 + (lane & 15)) * ROW_B + (lane >> 4) * 16);
    const uint32_t b_off = (uint32_t)(((lane & 7) + ((lane >> 4) & 1) * 8) * ROW_B +
                                      ((lane >> 3) & 1) * 16);

    issue(0, 0);       CP_COMMIT();
    issue(1, 64);      CP_COMMIT();

    const int NCH = NH / 64;
    for (int c = 0; c < NCH; c++) {
        if (c + 1 < NCH) CP_WAIT(1); else CP_WAIT(0);
        __syncthreads();
        uint32_t base = sb + (c % NSTAGE) * STAGE_B;
#pragma unroll
        for (int kk = 0; kk < 4; kk++) {
            uint32_t ah[4], al[4];
            LDSM4(ah, base + 0 * TILE_BB + a_off + kk * 32);
            LDSM4(al, base + 1 * TILE_BB + a_off + kk * 32);
#pragma unroll
            for (int nt = 0; nt < 8; nt++) {
                uint32_t bh[4], bl[4];
                uint32_t bo = b_off + nt * (16 * ROW_B) + kk * 32;
                LDSM4(bh, base + 2 * TILE_BB + bo);
                LDSM4(bl, base + 3 * TILE_BB + bo);
                MMA16816(acc[2 * nt],     ah, bh[0], bh[1]);
                MMA16816(acc[2 * nt],     ah, bl[0], bl[1]);
                MMA16816(acc[2 * nt],     al, bh[0], bh[1]);
                MMA16816(acc[2 * nt + 1], ah, bh[2], bh[3]);
                MMA16816(acc[2 * nt + 1], ah, bl[2], bl[3]);
                MMA16816(acc[2 * nt + 1], al, bh[2], bh[3]);
            }
        }
        __syncthreads();
        if (c + 2 < NCH) { issue((c + 2) % NSTAGE, (c + 2) * 64); CP_COMMIT(); }
    }

    // epilogue: cols 0..63 = gate(i0+j), 64..127 = up(i0+j); h = silu(g)*u
    const int r0 = m0 + wid * 16 + (lane >> 2);
    const int r1 = r0 + 8;
    const int cb = (lane & 3) * 2;
#pragma unroll
    for (int q = 0; q < 8; q++) {
        int col = i0 + q * 8 + cb;
#pragma unroll
        for (int half = 0; half < 2; half++) {
            int row = half ? r1 : r0;
            if (row >= M) continue;
            float g0 = acc[q][2 * half + 0],     g1 = acc[q][2 * half + 1];
            float u0 = acc[q + 8][2 * half + 0], u1 = acc[q + 8][2 * half + 1];
            float h0 = u0 * g0 / (1.f + __expf(-g0));
            float h1 = u1 * g1 / (1.f + __expf(-g1));
            __nv_bfloat16 hh0 = __float2bfloat16(h0), hh1 = __float2bfloat16(h1);
            __nv_bfloat162 ph; ph.x = hh0; ph.y = hh1;
            __nv_bfloat162 pl;
            pl.x = __float2bfloat16(h0 - __bfloat162float(hh0));
            pl.y = __float2bfloat16(h1 - __bfloat162float(hh1));
            size_t o = (size_t)(start + row) * NI + col;
            *(__nv_bfloat162*)(g_h_hi + o) = ph;
            *(__nv_bfloat162*)(g_h_lo + o) = pl;
        }
    }
}

// ---- GEMM2: C[128 slots, 128 hidden], K = NI, 22 chunks of 64; scatter-add ----
__global__ __launch_bounds__(256, 1) void k_gemm2(float* __restrict__ out) {
    extern __shared__ char smem[];
    const int e     = blockIdx.z;
    const int start = g_offsets[e];
    const int M     = g_offsets[e + 1] - start;
    const int m0    = blockIdx.y * 128;
    if (m0 >= M) return;
    const int n0 = blockIdx.x * 128;    // gridDim.x = NH/128 = 16

    const int tid  = threadIdx.x;
    const int wid  = tid >> 5;
    const int lane = tid & 31;
    uint32_t sb = smem_u32(smem);

    const int vrow = tid >> 3;
    const int col8 = tid & 7;
    size_t arow[4], brow[4];
#pragma unroll
    for (int i = 0; i < 4; i++) {
        int row = vrow + 32 * i;
        int ar  = m0 + row; if (ar >= M) ar = M - 1;
        arow[i] = (size_t)(start + ar) * NI;
        brow[i] = (size_t)e * NH * NI + (size_t)(n0 + row) * NI;
    }

    auto issue = [&](int s, int kk) {
        uint32_t base = sb + s * STAGE_B;
#pragma unroll
        for (int i = 0; i < 4; i++) {
            int row = vrow + 32 * i;
            uint32_t d = base + row * ROW_B + col8 * 16;
            CP_ASYNC16(d + 0 * TILE_BB, g_h_hi   + arow[i] + kk + col8 * 8);
            CP_ASYNC16(d + 1 * TILE_BB, g_h_lo   + arow[i] + kk + col8 * 8);
            CP_ASYNC16(d + 2 * TILE_BB, g_wdn_hi + brow[i] + kk + col8 * 8);
            CP_ASYNC16(d + 3 * TILE_BB, g_wdn_lo + brow[i] + kk + col8 * 8);
        }
    };

    float acc[16][4];
#pragma unroll
    for (int q = 0; q < 16; q++)
#pragma unroll
        for (int i = 0; i < 4; i++) acc[q][i] = 0.f;

    const uint32_t a_off = (uint32_t)((wid * 16 + (lane & 15)) * ROW_B + (lane >> 4) * 16);
    const uint32_t b_off = (uint32_t)(((lane & 7) + ((lane >> 4) & 1) * 8) * ROW_B +
                                      ((lane >> 3) & 1) * 16);

    issue(0, 0);       CP_COMMIT();
    issue(1, 64);      CP_COMMIT();

    const int NCH = NI / 64;
    for (int c = 0; c < NCH; c++) {
        if (c + 1 < NCH) CP_WAIT(1); else CP_WAIT(0);
        __syncthreads();
        uint32_t base = sb + (c % NSTAGE) * STAGE_B;
#pragma unroll
        for (int kk = 0; kk < 4; kk++) {
            uint32_t ah[4], al[4];
            LDSM4(ah, base + 0 * TILE_BB + a_off + kk * 32);
            LDSM4(al, base + 1 * TILE_BB + a_off + kk * 32);
#pragma unroll
            for (int nt = 0; nt < 8; nt++) {
                uint32_t bh[4], bl[4];
                uint32_t bo = b_off + nt * (16 * ROW_B) + kk * 32;
                LDSM4(bh, base + 2 * TILE_BB + bo);
                LDSM4(bl, base + 3 * TILE_BB + bo);
                MMA16816(acc[2 * nt],     ah, bh[0], bh[1]);
                MMA16816(acc[2 * nt],     ah, bl[0], bl[1]);
                MMA16816(acc[2 * nt],     al, bh[0], bh[1]);
                MMA16816(acc[2 * nt + 1], ah, bh[2], bh[3]);
                MMA16816(acc[2 * nt + 1], ah, bl[2], bl[3]);
                MMA16816(acc[2 * nt + 1], al, bh[2], bh[3]);
            }
        }
        __syncthreads();
        if (c + 2 < NCH) { issue((c + 2) % NSTAGE, (c + 2) * 64); CP_COMMIT(); }
    }

    // epilogue: out[tok, n0+col] += w * acc
    const int r0 = m0 + wid * 16 + (lane >> 2);
    const int r1 = r0 + 8;
    const int cb = (lane & 3) * 2;
#pragma unroll
    for (int half = 0; half < 2; half++) {
        int row = half ? r1 : r0;
        if (row >= M) continue;
        int   tok = g_slot_token[start + row];
        float w   = g_slot_w[start + row];
        float* orow = out + (size_t)tok * NH + n0;
#pragma unroll
        for (int q = 0; q < 16; q++) {
            atomicAdd(orow + q * 8 + cb + 0, w * acc[q][2 * half + 0]);
            atomicAdd(orow + q * 8 + cb + 1, w * acc[q][2 * half + 1]);
        }
    }
}

// ---------------- launch -----------------
extern "C" void kernel_launch(void* const* d_in, const int* in_sizes, int n_in,
                              void* d_out, int out_size) {
    const float* hidden = (const float*)d_in[0];   // [T, H]
    const void*  idx    = d_in[1];                 // [T, K] int32 or int64
    const float* wts    = (const float*)d_in[2];   // [T, K]
    const float* wgu    = (const float*)d_in[3];   // [E, 2I, H]
    const float* wdn    = (const float*)d_in[4];   // [E, H, I]
    (void)in_sizes; (void)n_in;

    cudaFuncSetAttribute(k_gemm1, cudaFuncAttributeMaxDynamicSharedMemorySize, SMEM_TOT);
    cudaFuncSetAttribute(k_gemm2, cudaFuncAttributeMaxDynamicSharedMemorySize, SMEM_TOT);

    // routing
    k_detect<<<1, 32>>>((const int*)idx);
    k_reset<<<1, 32>>>();
    k_count<<<(CAP + 255) / 256, 256>>>(idx);
    k_scan<<<1, 32>>>();
    k_scatter<<<(CAP + 255) / 256, 256>>>(idx, wts);

    // fp32 -> bf16 hi/lo splits
    k_cvt_hid<<<2048, 256>>>((const float4*)hidden);
    k_cvt_wgu<<<8192, 256>>>((const float4*)wgu);
    k_cvt_wdn<<<4096, 256>>>((const float4*)wdn);

    cudaMemsetAsync(d_out, 0, (size_t)out_size * sizeof(float), 0);

    // GEMM1: x = NI/64 = 22 tiles, y = worst-case M tiles, z = experts
    dim3 g1(NI / 64, CAP / 128, NE);
    k_gemm1<<<g1, 256, SMEM_TOT>>>();

    // GEMM2: x = NH/128 = 16 tiles
    dim3 g2(NH / 128, CAP / 128, NE);
    k_gemm2<<<g2, 256, SMEM_TOT>>>((float*)d_out);
}

// round 7
// speedup vs baseline: 1.7643x; 1.0175x over previous
#include <cuda_runtime.h>
#include <cuda_bf16.h>
#include <cstdint>

// Problem constants
#define NE 16
#define NH 2048
#define NI 1408
#define NK 2
#define NT 8192
#define CAP (NT * NK)   // 16384 routed slots

// ---------------- scratch (device globals; no cudaMalloc allowed) ----------
__device__ int   g_counts[NE];
__device__ int   g_fill[NE];
__device__ int   g_offsets[NE + 1];
__device__ int   g_slot_token[CAP];
__device__ float g_slot_w[CAP];
__device__ int   g_is64;

// bf16 split operands (hi + lo), K-major row layouts matching sources
__device__ __align__(16) __nv_bfloat16 g_hid_hi[(size_t)NT * NH];
__device__ __align__(16) __nv_bfloat16 g_hid_lo[(size_t)NT * NH];
__device__ __align__(16) __nv_bfloat16 g_wgu_hi[(size_t)NE * 2 * NI * NH];
__device__ __align__(16) __nv_bfloat16 g_wgu_lo[(size_t)NE * 2 * NI * NH];
__device__ __align__(16) __nv_bfloat16 g_wdn_hi[(size_t)NE * NH * NI];
__device__ __align__(16) __nv_bfloat16 g_wdn_lo[(size_t)NE * NH * NI];
__device__ __align__(16) __nv_bfloat16 g_h_hi[(size_t)CAP * NI];
__device__ __align__(16) __nv_bfloat16 g_h_lo[(size_t)CAP * NI];

// ---------------- PTX helpers (baseline ISA only: sm_80+ features) ---------
__device__ __forceinline__ uint32_t smem_u32(const void* p) {
    uint32_t a;
    asm("{ .reg .u64 t; cvta.to.shared.u64 t, %1; cvt.u32.u64 %0, t; }" : "=r"(a) : "l"(p));
    return a;
}
#define CP_ASYNC16(dst, src) \
    asm volatile("cp.async.cg.shared.global [%0], [%1], 16;" :: "r"(dst), "l"(src))
#define CP_COMMIT() asm volatile("cp.async.commit_group;" ::: "memory")
#define CP_WAIT(N)  asm volatile("cp.async.wait_group %0;" :: "n"(N) : "memory")

#define LDSM4(r, addr) \
    asm volatile("ldmatrix.sync.aligned.m8n8.x4.shared.b16 {%0,%1,%2,%3}, [%4];" \
        : "=r"((r)[0]), "=r"((r)[1]), "=r"((r)[2]), "=r"((r)[3]) : "r"(addr))

#define MMA16816(c, a, b0_, b1_) \
    asm volatile("mma.sync.aligned.m16n8k16.row.col.f32.bf16.bf16.f32 " \
        "{%0,%1,%2,%3}, {%4,%5,%6,%7}, {%8,%9}, {%0,%1,%2,%3};" \
        : "+f"((c)[0]), "+f"((c)[1]), "+f"((c)[2]), "+f"((c)[3]) \
        : "r"((a)[0]), "r"((a)[1]), "r"((a)[2]), "r"((a)[3]), "r"(b0_), "r"(b1_))

// ---------------- dtype detection for top_k_index -----------------
__global__ void k_detect(const int* __restrict__ idx32) {
    if (threadIdx.x == 0) {
        int is64 = 1;
        for (int i = 0; i < 256; i++) {
            int lo = idx32[2 * i], hi = idx32[2 * i + 1];
            if (hi != 0 || lo < 0 || lo >= NE) { is64 = 0; break; }
        }
        g_is64 = is64;
    }
}
__device__ __forceinline__ int load_expert(const void* idx, int s) {
    if (g_is64) return (int)((const long long*)idx)[s];
    return ((const int*)idx)[s];
}

// ---------------- routing -----------------
__global__ void k_reset() {
    int i = threadIdx.x;
    if (i < NE) { g_counts[i] = 0; g_fill[i] = 0; }
}
__global__ void k_count(const void* __restrict__ idx) {
    int s = blockIdx.x * blockDim.x + threadIdx.x;
    if (s < CAP) {
        int e = load_expert(idx, s);
        if (e >= 0 && e < NE) atomicAdd(&g_counts[e], 1);
    }
}
__global__ void k_scan() {
    if (threadIdx.x == 0) {
        int acc = 0;
        for (int e = 0; e < NE; e++) { g_offsets[e] = acc; acc += g_counts[e]; }
        g_offsets[NE] = acc;
    }
}
__global__ void k_scatter(const void* __restrict__ idx, const float* __restrict__ w) {
    int s = blockIdx.x * blockDim.x + threadIdx.x;
    if (s < CAP) {
        int e = load_expert(idx, s);
        if (e >= 0 && e < NE) {
            int p = g_offsets[e] + atomicAdd(&g_fill[e], 1);
            g_slot_token[p] = s / NK;
            g_slot_w[p]     = w[s];
        }
    }
}

// ---------------- fp32 -> bf16 hi/lo split conversions ----------------
__device__ __forceinline__ void cvt_body(const float4* __restrict__ s,
                                         __nv_bfloat162* __restrict__ hi,
                                         __nv_bfloat162* __restrict__ lo, size_t n4) {
    size_t i = (size_t)blockIdx.x * blockDim.x + threadIdx.x;
    size_t stride = (size_t)gridDim.x * blockDim.x;
    for (; i < n4; i += stride) {
        float4 v = s[i];
        __nv_bfloat16 hx = __float2bfloat16(v.x), hy = __float2bfloat16(v.y);
        __nv_bfloat16 hz = __float2bfloat16(v.z), hw = __float2bfloat16(v.w);
        __nv_bfloat162 h0; h0.x = hx; h0.y = hy;
        __nv_bfloat162 h1; h1.x = hz; h1.y = hw;
        hi[2 * i]     = h0;
        hi[2 * i + 1] = h1;
        __nv_bfloat162 l0, l1;
        l0.x = __float2bfloat16(v.x - __bfloat162float(hx));
        l0.y = __float2bfloat16(v.y - __bfloat162float(hy));
        l1.x = __float2bfloat16(v.z - __bfloat162float(hz));
        l1.y = __float2bfloat16(v.w - __bfloat162float(hw));
        lo[2 * i]     = l0;
        lo[2 * i + 1] = l1;
    }
}
__global__ void k_cvt_hid(const float4* __restrict__ s) {
    cvt_body(s, (__nv_bfloat162*)g_hid_hi, (__nv_bfloat162*)g_hid_lo, (size_t)NT * NH / 4);
}
__global__ void k_cvt_wgu(const float4* __restrict__ s) {
    cvt_body(s, (__nv_bfloat162*)g_wgu_hi, (__nv_bfloat162*)g_wgu_lo, (size_t)NE * 2 * NI * NH / 4);
}
__global__ void k_cvt_wdn(const float4* __restrict__ s) {
    cvt_body(s, (__nv_bfloat162*)g_wdn_hi, (__nv_bfloat162*)g_wdn_lo, (size_t)NE * NH * NI / 4);
}

// ---------------- HMMA GEMMs ----------------
// M-tile 256 x N-tile 128, K-chunks of 64.
// SMEM per stage: Ah, Al (256 x 64 bf16) + Bh, Bl (128 x 64 bf16),
// row stride 72 elems (144 B; conflict-free ldmatrix), 2 stages.
#define ROW_B   144
#define A_TB    (256 * ROW_B)               // 36864 B
#define B_TB    (128 * ROW_B)               // 18432 B
#define STAGE_B (2 * A_TB + 2 * B_TB)       // 110592 B
#define SMEM_TOT (2 * STAGE_B)              // 221184 B
// stage-local offsets
#define OFF_AH 0
#define OFF_AL A_TB
#define OFF_BH (2 * A_TB)
#define OFF_BL (2 * A_TB + B_TB)

// Warp layout: 8 warps, warp w owns rows [w*32, w*32+32) (2 m16 frags), all 128 N.
// Per k16 step: 4 A LDSM + 16 B LDSM, 96 MMAs.

// ---- GEMM1: C[256 slots, 64 gate | 64 up], K = NH, 32 chunks of 64 ----
__global__ __launch_bounds__(256, 1) void k_gemm1() {
    extern __shared__ char smem[];
    const int e     = blockIdx.z;
    const int start = g_offsets[e];
    const int M     = g_offsets[e + 1] - start;
    const int m0    = blockIdx.y * 256;
    if (m0 >= M) return;
    const int i0 = blockIdx.x * 64;     // gridDim.x = NI/64 = 22

    const int tid  = threadIdx.x;
    const int wid  = tid >> 5;
    const int lane = tid & 31;
    uint32_t sb = smem_u32(smem);

    const int vrow = tid >> 3;          // 0..31
    const int col8 = tid & 7;
    size_t arow[8], brow[4];
#pragma unroll
    for (int i = 0; i < 8; i++) {
        int row = vrow + 32 * i;        // 0..255
        int ar  = m0 + row; if (ar >= M) ar = M - 1;
        arow[i] = (size_t)g_slot_token[start + ar] * NH;
    }
#pragma unroll
    for (int i = 0; i < 4; i++) {
        int rb = vrow + 32 * i;         // 0..127
        int wr = (rb < 64) ? (i0 + rb) : (NI + i0 + rb - 64);
        brow[i] = (size_t)e * (2 * NI) * NH + (size_t)wr * NH;
    }

    auto issue = [&](int s, int kk) {
        uint32_t base = sb + s * STAGE_B;
#pragma unroll
        for (int i = 0; i < 8; i++) {
            int row = vrow + 32 * i;
            uint32_t d = base + row * ROW_B + col8 * 16;
            CP_ASYNC16(d + OFF_AH, g_hid_hi + arow[i] + kk + col8 * 8);
            CP_ASYNC16(d + OFF_AL, g_hid_lo + arow[i] + kk + col8 * 8);
        }
#pragma unroll
        for (int i = 0; i < 4; i++) {
            int rb = vrow + 32 * i;
            uint32_t d = base + rb * ROW_B + col8 * 16;
            CP_ASYNC16(d + OFF_BH, g_wgu_hi + brow[i] + kk + col8 * 8);
            CP_ASYNC16(d + OFF_BL, g_wgu_lo + brow[i] + kk + col8 * 8);
        }
    };

    float acc[2][16][4];
#pragma unroll
    for (int mf = 0; mf < 2; mf++)
#pragma unroll
        for (int q = 0; q < 16; q++)
#pragma unroll
            for (int i = 0; i < 4; i++) acc[mf][q][i] = 0.f;

    const uint32_t a_base = (uint32_t)((wid * 32 + (lane & 15)) * ROW_B + (lane >> 4) * 16);
    const uint32_t b_off  = (uint32_t)(((lane & 7) + ((lane >> 4) & 1) * 8) * ROW_B +
                                       ((lane >> 3) & 1) * 16);

    issue(0, 0);
    CP_COMMIT();

    const int NCH = NH / 64;
    for (int c = 0; c < NCH; c++) {
        if (c + 1 < NCH) { issue((c + 1) & 1, (c + 1) * 64); CP_COMMIT(); CP_WAIT(1); }
        else             { CP_WAIT(0); }
        __syncthreads();
        uint32_t base = sb + (c & 1) * STAGE_B;
#pragma unroll
        for (int kk = 0; kk < 4; kk++) {
            uint32_t ah0[4], al0[4], ah1[4], al1[4];
            LDSM4(ah0, base + OFF_AH + a_base + kk * 32);
            LDSM4(al0, base + OFF_AL + a_base + kk * 32);
            LDSM4(ah1, base + OFF_AH + a_base + 16 * ROW_B + kk * 32);
            LDSM4(al1, base + OFF_AL + a_base + 16 * ROW_B + kk * 32);
#pragma unroll
            for (int nt = 0; nt < 8; nt++) {
                uint32_t bh[4], bl[4];
                uint32_t bo = b_off + nt * (16 * ROW_B) + kk * 32;
                LDSM4(bh, base + OFF_BH + bo);
                LDSM4(bl, base + OFF_BL + bo);
                MMA16816(acc[0][2 * nt],     ah0, bh[0], bh[1]);
                MMA16816(acc[0][2 * nt],     ah0, bl[0], bl[1]);
                MMA16816(acc[0][2 * nt],     al0, bh[0], bh[1]);
                MMA16816(acc[0][2 * nt + 1], ah0, bh[2], bh[3]);
                MMA16816(acc[0][2 * nt + 1], ah0, bl[2], bl[3]);
                MMA16816(acc[0][2 * nt + 1], al0, bh[2], bh[3]);
                MMA16816(acc[1][2 * nt],     ah1, bh[0], bh[1]);
                MMA16816(acc[1][2 * nt],     ah1, bl[0], bl[1]);
                MMA16816(acc[1][2 * nt],     al1, bh[0], bh[1]);
                MMA16816(acc[1][2 * nt + 1], ah1, bh[2], bh[3]);
                MMA16816(acc[1][2 * nt + 1], ah1, bl[2], bl[3]);
                MMA16816(acc[1][2 * nt + 1], al1, bh[2], bh[3]);
            }
        }
        __syncthreads();
    }

    // epilogue: cols 0..63 = gate(i0+j), 64..127 = up(i0+j); h = silu(g)*u
    const int cb = (lane & 3) * 2;
#pragma unroll
    for (int mf = 0; mf < 2; mf++) {
        int rbase = m0 + wid * 32 + mf * 16 + (lane >> 2);
#pragma unroll
        for (int q = 0; q < 8; q++) {
            int col = i0 + q * 8 + cb;
#pragma unroll
            for (int half = 0; half < 2; half++) {
                int row = rbase + half * 8;
                if (row >= M) continue;
                float g0 = acc[mf][q][2 * half + 0],     g1 = acc[mf][q][2 * half + 1];
                float u0 = acc[mf][q + 8][2 * half + 0], u1 = acc[mf][q + 8][2 * half + 1];
                float h0 = u0 * g0 / (1.f + __expf(-g0));
                float h1 = u1 * g1 / (1.f + __expf(-g1));
                __nv_bfloat16 hh0 = __float2bfloat16(h0), hh1 = __float2bfloat16(h1);
                __nv_bfloat162 ph; ph.x = hh0; ph.y = hh1;
                __nv_bfloat162 pl;
                pl.x = __float2bfloat16(h0 - __bfloat162float(hh0));
                pl.y = __float2bfloat16(h1 - __bfloat162float(hh1));
                size_t o = (size_t)(start + row) * NI + col;
                *(__nv_bfloat162*)(g_h_hi + o) = ph;
                *(__nv_bfloat162*)(g_h_lo + o) = pl;
            }
        }
    }
}

// ---- GEMM2: C[256 slots, 128 hidden], K = NI, 22 chunks of 64; scatter-add ----
__global__ __launch_bounds__(256, 1) void k_gemm2(float* __restrict__ out) {
    extern __shared__ char smem[];
    const int e     = blockIdx.z;
    const int start = g_offsets[e];
    const int M     = g_offsets[e + 1] - start;
    const int m0    = blockIdx.y * 256;
    if (m0 >= M) return;
    const int n0 = blockIdx.x * 128;    // gridDim.x = NH/128 = 16

    const int tid  = threadIdx.x;
    const int wid  = tid >> 5;
    const int lane = tid & 31;
    uint32_t sb = smem_u32(smem);

    const int vrow = tid >> 3;
    const int col8 = tid & 7;
    size_t arow[8], brow[4];
#pragma unroll
    for (int i = 0; i < 8; i++) {
        int row = vrow + 32 * i;
        int ar  = m0 + row; if (ar >= M) ar = M - 1;
        arow[i] = (size_t)(start + ar) * NI;
    }
#pragma unroll
    for (int i = 0; i < 4; i++) {
        int rb = vrow + 32 * i;
        brow[i] = (size_t)e * NH * NI + (size_t)(n0 + rb) * NI;
    }

    auto issue = [&](int s, int kk) {
        uint32_t base = sb + s * STAGE_B;
#pragma unroll
        for (int i = 0; i < 8; i++) {
            int row = vrow + 32 * i;
            uint32_t d = base + row * ROW_B + col8 * 16;
            CP_ASYNC16(d + OFF_AH, g_h_hi + arow[i] + kk + col8 * 8);
            CP_ASYNC16(d + OFF_AL, g_h_lo + arow[i] + kk + col8 * 8);
        }
#pragma unroll
        for (int i = 0; i < 4; i++) {
            int rb = vrow + 32 * i;
            uint32_t d = base + rb * ROW_B + col8 * 16;
            CP_ASYNC16(d + OFF_BH, g_wdn_hi + brow[i] + kk + col8 * 8);
            CP_ASYNC16(d + OFF_BL, g_wdn_lo + brow[i] + kk + col8 * 8);
        }
    };

    float acc[2][16][4];
#pragma unroll
    for (int mf = 0; mf < 2; mf++)
#pragma unroll
        for (int q = 0; q < 16; q++)
#pragma unroll
            for (int i = 0; i < 4; i++) acc[mf][q][i] = 0.f;

    const uint32_t a_base = (uint32_t)((wid * 32 + (lane & 15)) * ROW_B + (lane >> 4) * 16);
    const uint32_t b_off  = (uint32_t)(((lane & 7) + ((lane >> 4) & 1) * 8) * ROW_B +
                                       ((lane >> 3) & 1) * 16);

    issue(0, 0);
    CP_COMMIT();

    const int NCH = NI / 64;
    for (int c = 0; c < NCH; c++) {
        if (c + 1 < NCH) { issue((c + 1) & 1, (c + 1) * 64); CP_COMMIT(); CP_WAIT(1); }
        else             { CP_WAIT(0); }
        __syncthreads();
        uint32_t base = sb + (c & 1) * STAGE_B;
#pragma unroll
        for (int kk = 0; kk < 4; kk++) {
            uint32_t ah0[4], al0[4], ah1[4], al1[4];
            LDSM4(ah0, base + OFF_AH + a_base + kk * 32);
            LDSM4(al0, base + OFF_AL + a_base + kk * 32);
            LDSM4(ah1, base + OFF_AH + a_base + 16 * ROW_B + kk * 32);
            LDSM4(al1, base + OFF_AL + a_base + 16 * ROW_B + kk * 32);
#pragma unroll
            for (int nt = 0; nt < 8; nt++) {
                uint32_t bh[4], bl[4];
                uint32_t bo = b_off + nt * (16 * ROW_B) + kk * 32;
                LDSM4(bh, base + OFF_BH + bo);
                LDSM4(bl, base + OFF_BL + bo);
                MMA16816(acc[0][2 * nt],     ah0, bh[0], bh[1]);
                MMA16816(acc[0][2 * nt],     ah0, bl[0], bl[1]);
                MMA16816(acc[0][2 * nt],     al0, bh[0], bh[1]);
                MMA16816(acc[0][2 * nt + 1], ah0, bh[2], bh[3]);
                MMA16816(acc[0][2 * nt + 1], ah0, bl[2], bl[3]);
                MMA16816(acc[0][2 * nt + 1], al0, bh[2], bh[3]);
                MMA16816(acc[1][2 * nt],     ah1, bh[0], bh[1]);
                MMA16816(acc[1][2 * nt],     ah1, bl[0], bl[1]);
                MMA16816(acc[1][2 * nt],     al1, bh[0], bh[1]);
                MMA16816(acc[1][2 * nt + 1], ah1, bh[2], bh[3]);
                MMA16816(acc[1][2 * nt + 1], ah1, bl[2], bl[3]);
                MMA16816(acc[1][2 * nt + 1], al1, bh[2], bh[3]);
            }
        }
        __syncthreads();
    }

    // epilogue: out[tok, n0+col] += w * acc
    const int cb = (lane & 3) * 2;
#pragma unroll
    for (int mf = 0; mf < 2; mf++) {
        int rbase = m0 + wid * 32 + mf * 16 + (lane >> 2);
#pragma unroll
        for (int half = 0; half < 2; half++) {
            int row = rbase + half * 8;
            if (row >= M) continue;
            int   tok = g_slot_token[start + row];
            float w   = g_slot_w[start + row];
            float* orow = out + (size_t)tok * NH + n0;
#pragma unroll
            for (int q = 0; q < 16; q++) {
                atomicAdd(orow + q * 8 + cb + 0, w * acc[mf][q][2 * half + 0]);
                atomicAdd(orow + q * 8 + cb + 1, w * acc[mf][q][2 * half + 1]);
            }
        }
    }
}

// ---------------- launch -----------------
extern "C" void kernel_launch(void* const* d_in, const int* in_sizes, int n_in,
                              void* d_out, int out_size) {
    const float* hidden = (const float*)d_in[0];   // [T, H]
    const void*  idx    = d_in[1];                 // [T, K] int32 or int64
    const float* wts    = (const float*)d_in[2];   // [T, K]
    const float* wgu    = (const float*)d_in[3];   // [E, 2I, H]
    const float* wdn    = (const float*)d_in[4];   // [E, H, I]
    (void)in_sizes; (void)n_in;

    cudaFuncSetAttribute(k_gemm1, cudaFuncAttributeMaxDynamicSharedMemorySize, SMEM_TOT);
    cudaFuncSetAttribute(k_gemm2, cudaFuncAttributeMaxDynamicSharedMemorySize, SMEM_TOT);

    // routing
    k_detect<<<1, 32>>>((const int*)idx);
    k_reset<<<1, 32>>>();
    k_count<<<(CAP + 255) / 256, 256>>>(idx);
    k_scan<<<1, 32>>>();
    k_scatter<<<(CAP + 255) / 256, 256>>>(idx, wts);

    // fp32 -> bf16 hi/lo splits
    k_cvt_hid<<<2048, 256>>>((const float4*)hidden);
    k_cvt_wgu<<<8192, 256>>>((const float4*)wgu);
    k_cvt_wdn<<<4096, 256>>>((const float4*)wdn);

    cudaMemsetAsync(d_out, 0, (size_t)out_size * sizeof(float), 0);

    // GEMM1: x = NI/64 = 22 tiles, y = worst-case M tiles (256 rows), z = experts
    dim3 g1(NI / 64, CAP / 256, NE);
    k_gemm1<<<g1, 256, SMEM_TOT>>>();

    // GEMM2: x = NH/128 = 16 tiles
    dim3 g2(NH / 128, CAP / 256, NE);
    k_gemm2<<<g2, 256, SMEM_TOT>>>((float*)d_out);
}

// round 8
// speedup vs baseline: 2.3742x; 1.3457x over previous
#include <cuda_runtime.h>
#include <cuda_fp16.h>
#include <cstdint>

// Problem constants
#define NE 16
#define NH 2048
#define NI 1408
#define NK 2
#define NT 8192
#define CAP (NT * NK)   // 16384 routed slots

// ---------------- scratch (device globals; no cudaMalloc allowed) ----------
__device__ int   g_counts[NE];
__device__ int   g_fill[NE];
__device__ int   g_offsets[NE + 1];
__device__ int   g_slot_token[CAP];
__device__ float g_slot_w[CAP];
__device__ int   g_is64;

// fp16 operands: activations split hi+lo (~22 bits), weights rounded (11 bits)
__device__ __align__(16) __half g_hid_hi[(size_t)NT * NH];
__device__ __align__(16) __half g_hid_lo[(size_t)NT * NH];
__device__ __align__(16) __half g_wgu_h[(size_t)NE * 2 * NI * NH];
__device__ __align__(16) __half g_wdn_h[(size_t)NE * NH * NI];
__device__ __align__(16) __half g_h_hi[(size_t)CAP * NI];
__device__ __align__(16) __half g_h_lo[(size_t)CAP * NI];

// ---------------- PTX helpers (baseline ISA only: sm_80+ features) ---------
__device__ __forceinline__ uint32_t smem_u32(const void* p) {
    uint32_t a;
    asm("{ .reg .u64 t; cvta.to.shared.u64 t, %1; cvt.u32.u64 %0, t; }" : "=r"(a) : "l"(p));
    return a;
}
#define CP_ASYNC16(dst, src) \
    asm volatile("cp.async.cg.shared.global [%0], [%1], 16;" :: "r"(dst), "l"(src))
#define CP_COMMIT() asm volatile("cp.async.commit_group;" ::: "memory")
#define CP_WAIT(N)  asm volatile("cp.async.wait_group %0;" :: "n"(N) : "memory")

#define LDSM4(r, addr) \
    asm volatile("ldmatrix.sync.aligned.m8n8.x4.shared.b16 {%0,%1,%2,%3}, [%4];" \
        : "=r"((r)[0]), "=r"((r)[1]), "=r"((r)[2]), "=r"((r)[3]) : "r"(addr))

#define MMA16816(c, a, b0_, b1_) \
    asm volatile("mma.sync.aligned.m16n8k16.row.col.f32.f16.f16.f32 " \
        "{%0,%1,%2,%3}, {%4,%5,%6,%7}, {%8,%9}, {%0,%1,%2,%3};" \
        : "+f"((c)[0]), "+f"((c)[1]), "+f"((c)[2]), "+f"((c)[3]) \
        : "r"((a)[0]), "r"((a)[1]), "r"((a)[2]), "r"((a)[3]), "r"(b0_), "r"(b1_))

// ---------------- dtype detection for top_k_index -----------------
__global__ void k_detect(const int* __restrict__ idx32) {
    if (threadIdx.x == 0) {
        int is64 = 1;
        for (int i = 0; i < 256; i++) {
            int lo = idx32[2 * i], hi = idx32[2 * i + 1];
            if (hi != 0 || lo < 0 || lo >= NE) { is64 = 0; break; }
        }
        g_is64 = is64;
    }
}
__device__ __forceinline__ int load_expert(const void* idx, int s) {
    if (g_is64) return (int)((const long long*)idx)[s];
    return ((const int*)idx)[s];
}

// ---------------- routing -----------------
__global__ void k_reset() {
    int i = threadIdx.x;
    if (i < NE) { g_counts[i] = 0; g_fill[i] = 0; }
}
__global__ void k_count(const void* __restrict__ idx) {
    int s = blockIdx.x * blockDim.x + threadIdx.x;
    if (s < CAP) {
        int e = load_expert(idx, s);
        if (e >= 0 && e < NE) atomicAdd(&g_counts[e], 1);
    }
}
__global__ void k_scan() {
    if (threadIdx.x == 0) {
        int acc = 0;
        for (int e = 0; e < NE; e++) { g_offsets[e] = acc; acc += g_counts[e]; }
        g_offsets[NE] = acc;
    }
}
__global__ void k_scatter(const void* __restrict__ idx, const float* __restrict__ w) {
    int s = blockIdx.x * blockDim.x + threadIdx.x;
    if (s < CAP) {
        int e = load_expert(idx, s);
        if (e >= 0 && e < NE) {
            int p = g_offsets[e] + atomicAdd(&g_fill[e], 1);
            g_slot_token[p] = s / NK;
            g_slot_w[p]     = w[s];
        }
    }
}

// ---------------- fp32 -> fp16 conversions ----------------
// split: hi = fp16(x), lo = fp16(x - hi)
__global__ void k_cvt_hid(const float4* __restrict__ s) {
    __half2* hi = (__half2*)g_hid_hi;
    __half2* lo = (__half2*)g_hid_lo;
    size_t n4 = (size_t)NT * NH / 4;
    size_t i = (size_t)blockIdx.x * blockDim.x + threadIdx.x;
    size_t stride = (size_t)gridDim.x * blockDim.x;
    for (; i < n4; i += stride) {
        float4 v = s[i];
        __half hx = __float2half(v.x), hy = __float2half(v.y);
        __half hz = __float2half(v.z), hw = __float2half(v.w);
        hi[2 * i]     = __halves2half2(hx, hy);
        hi[2 * i + 1] = __halves2half2(hz, hw);
        lo[2 * i]     = __halves2half2(__float2half(v.x - __half2float(hx)),
                                       __float2half(v.y - __half2float(hy)));
        lo[2 * i + 1] = __halves2half2(__float2half(v.z - __half2float(hz)),
                                       __float2half(v.w - __half2float(hw)));
    }
}
// round-only for weights
__device__ __forceinline__ void cvt_round_body(const float4* __restrict__ s,
                                               __half2* __restrict__ hi, size_t n4) {
    size_t i = (size_t)blockIdx.x * blockDim.x + threadIdx.x;
    size_t stride = (size_t)gridDim.x * blockDim.x;
    for (; i < n4; i += stride) {
        float4 v = s[i];
        hi[2 * i]     = __halves2half2(__float2half(v.x), __float2half(v.y));
        hi[2 * i + 1] = __halves2half2(__float2half(v.z), __float2half(v.w));
    }
}
__global__ void k_cvt_wgu(const float4* __restrict__ s) {
    cvt_round_body(s, (__half2*)g_wgu_h, (size_t)NE * 2 * NI * NH / 4);
}
__global__ void k_cvt_wdn(const float4* __restrict__ s) {
    cvt_round_body(s, (__half2*)g_wdn_h, (size_t)NE * NH * NI / 4);
}

// ---------------- HMMA GEMMs ----------------
// M-tile 256 x N-tile 128, K-chunks of 64.
// SMEM per stage: Ah, Al (256 x 64 fp16) + Bh (128 x 64 fp16),
// row stride 72 elems (144 B; conflict-free ldmatrix), 2 stages.
#define ROW_B   144
#define A_TB    (256 * ROW_B)               // 36864 B
#define B_TB    (128 * ROW_B)               // 18432 B
#define STAGE_B (2 * A_TB + B_TB)           // 92160 B
#define SMEM_TOT (2 * STAGE_B)              // 184320 B
#define OFF_AH 0
#define OFF_AL A_TB
#define OFF_BH (2 * A_TB)

// Warp layout: 8 warps, warp w owns rows [w*32, w*32+32) (2 m16 frags), all 128 N.
// Per k16 step: 4 A LDSM + 8 B LDSM, 64 MMAs.

// ---- GEMM1: C[256 slots, 64 gate | 64 up], K = NH, 32 chunks of 64 ----
__global__ __launch_bounds__(256, 1) void k_gemm1() {
    extern __shared__ char smem[];
    const int e     = blockIdx.z;
    const int start = g_offsets[e];
    const int M     = g_offsets[e + 1] - start;
    const int m0    = blockIdx.y * 256;
    if (m0 >= M) return;
    const int i0 = blockIdx.x * 64;     // gridDim.x = NI/64 = 22

    const int tid  = threadIdx.x;
    const int wid  = tid >> 5;
    const int lane = tid & 31;
    uint32_t sb = smem_u32(smem);

    const int vrow = tid >> 3;          // 0..31
    const int col8 = tid & 7;
    size_t arow[8], brow[4];
#pragma unroll
    for (int i = 0; i < 8; i++) {
        int row = vrow + 32 * i;        // 0..255
        int ar  = m0 + row; if (ar >= M) ar = M - 1;
        arow[i] = (size_t)g_slot_token[start + ar] * NH;
    }
#pragma unroll
    for (int i = 0; i < 4; i++) {
        int rb = vrow + 32 * i;         // 0..127
        int wr = (rb < 64) ? (i0 + rb) : (NI + i0 + rb - 64);
        brow[i] = (size_t)e * (2 * NI) * NH + (size_t)wr * NH;
    }

    auto issue = [&](int s, int kk) {
        uint32_t base = sb + s * STAGE_B;
#pragma unroll
        for (int i = 0; i < 8; i++) {
            int row = vrow + 32 * i;
            uint32_t d = base + row * ROW_B + col8 * 16;
            CP_ASYNC16(d + OFF_AH, g_hid_hi + arow[i] + kk + col8 * 8);
            CP_ASYNC16(d + OFF_AL, g_hid_lo + arow[i] + kk + col8 * 8);
        }
#pragma unroll
        for (int i = 0; i < 4; i++) {
            int rb = vrow + 32 * i;
            uint32_t d = base + rb * ROW_B + col8 * 16;
            CP_ASYNC16(d + OFF_BH, g_wgu_h + brow[i] + kk + col8 * 8);
        }
    };

    float acc[2][16][4];
#pragma unroll
    for (int mf = 0; mf < 2; mf++)
#pragma unroll
        for (int q = 0; q < 16; q++)
#pragma unroll
            for (int i = 0; i < 4; i++) acc[mf][q][i] = 0.f;

    const uint32_t a_base = (uint32_t)((wid * 32 + (lane & 15)) * ROW_B + (lane >> 4) * 16);
    const uint32_t b_off  = (uint32_t)(((lane & 7) + ((lane >> 4) & 1) * 8) * ROW_B +
                                       ((lane >> 3) & 1) * 16);

    issue(0, 0);
    CP_COMMIT();

    const int NCH = NH / 64;
    for (int c = 0; c < NCH; c++) {
        if (c + 1 < NCH) { issue((c + 1) & 1, (c + 1) * 64); CP_COMMIT(); CP_WAIT(1); }
        else             { CP_WAIT(0); }
        __syncthreads();
        uint32_t base = sb + (c & 1) * STAGE_B;
#pragma unroll
        for (int kk = 0; kk < 4; kk++) {
            uint32_t ah0[4], al0[4], ah1[4], al1[4];
            LDSM4(ah0, base + OFF_AH + a_base + kk * 32);
            LDSM4(al0, base + OFF_AL + a_base + kk * 32);
            LDSM4(ah1, base + OFF_AH + a_base + 16 * ROW_B + kk * 32);
            LDSM4(al1, base + OFF_AL + a_base + 16 * ROW_B + kk * 32);
#pragma unroll
            for (int nt = 0; nt < 8; nt++) {
                uint32_t bh[4];
                uint32_t bo = b_off + nt * (16 * ROW_B) + kk * 32;
                LDSM4(bh, base + OFF_BH + bo);
                MMA16816(acc[0][2 * nt],     ah0, bh[0], bh[1]);
                MMA16816(acc[0][2 * nt],     al0, bh[0], bh[1]);
                MMA16816(acc[0][2 * nt + 1], ah0, bh[2], bh[3]);
                MMA16816(acc[0][2 * nt + 1], al0, bh[2], bh[3]);
                MMA16816(acc[1][2 * nt],     ah1, bh[0], bh[1]);
                MMA16816(acc[1][2 * nt],     al1, bh[0], bh[1]);
                MMA16816(acc[1][2 * nt + 1], ah1, bh[2], bh[3]);
                MMA16816(acc[1][2 * nt + 1], al1, bh[2], bh[3]);
            }
        }
        __syncthreads();
    }

    // epilogue: cols 0..63 = gate(i0+j), 64..127 = up(i0+j); h = silu(g)*u
    const int cb = (lane & 3) * 2;
#pragma unroll
    for (int mf = 0; mf < 2; mf++) {
        int rbase = m0 + wid * 32 + mf * 16 + (lane >> 2);
#pragma unroll
        for (int q = 0; q < 8; q++) {
            int col = i0 + q * 8 + cb;
#pragma unroll
            for (int half = 0; half < 2; half++) {
                int row = rbase + half * 8;
                if (row >= M) continue;
                float g0 = acc[mf][q][2 * half + 0],     g1 = acc[mf][q][2 * half + 1];
                float u0 = acc[mf][q + 8][2 * half + 0], u1 = acc[mf][q + 8][2 * half + 1];
                float h0 = u0 * g0 / (1.f + __expf(-g0));
                float h1 = u1 * g1 / (1.f + __expf(-g1));
                __half hh0 = __float2half(h0), hh1 = __float2half(h1);
                __half2 ph = __halves2half2(hh0, hh1);
                __half2 pl = __halves2half2(__float2half(h0 - __half2float(hh0)),
                                            __float2half(h1 - __half2float(hh1)));
                size_t o = (size_t)(start + row) * NI + col;
                *(__half2*)(g_h_hi + o) = ph;
                *(__half2*)(g_h_lo + o) = pl;
            }
        }
    }
}

// ---- GEMM2: C[256 slots, 128 hidden], K = NI, 22 chunks of 64; scatter-add ----
__global__ __launch_bounds__(256, 1) void k_gemm2(float* __restrict__ out) {
    extern __shared__ char smem[];
    const int e     = blockIdx.z;
    const int start = g_offsets[e];
    const int M     = g_offsets[e + 1] - start;
    const int m0    = blockIdx.y * 256;
    if (m0 >= M) return;
    const int n0 = blockIdx.x * 128;    // gridDim.x = NH/128 = 16

    const int tid  = threadIdx.x;
    const int wid  = tid >> 5;
    const int lane = tid & 31;
    uint32_t sb = smem_u32(smem);

    const int vrow = tid >> 3;
    const int col8 = tid & 7;
    size_t arow[8], brow[4];
#pragma unroll
    for (int i = 0; i < 8; i++) {
        int row = vrow + 32 * i;
        int ar  = m0 + row; if (ar >= M) ar = M - 1;
        arow[i] = (size_t)(start + ar) * NI;
    }
#pragma unroll
    for (int i = 0; i < 4; i++) {
        int rb = vrow + 32 * i;
        brow[i] = (size_t)e * NH * NI + (size_t)(n0 + rb) * NI;
    }

    auto issue = [&](int s, int kk) {
        uint32_t base = sb + s * STAGE_B;
#pragma unroll
        for (int i = 0; i < 8; i++) {
            int row = vrow + 32 * i;
            uint32_t d = base + row * ROW_B + col8 * 16;
            CP_ASYNC16(d + OFF_AH, g_h_hi + arow[i] + kk + col8 * 8);
            CP_ASYNC16(d + OFF_AL, g_h_lo + arow[i] + kk + col8 * 8);
        }
#pragma unroll
        for (int i = 0; i < 4; i++) {
            int rb = vrow + 32 * i;
            uint32_t d = base + rb * ROW_B + col8 * 16;
            CP_ASYNC16(d + OFF_BH, g_wdn_h + brow[i] + kk + col8 * 8);
        }
    };

    float acc[2][16][4];
#pragma unroll
    for (int mf = 0; mf < 2; mf++)
#pragma unroll
        for (int q = 0; q < 16; q++)
#pragma unroll
            for (int i = 0; i < 4; i++) acc[mf][q][i] = 0.f;

    const uint32_t a_base = (uint32_t)((wid * 32 + (lane & 15)) * ROW_B + (lane >> 4) * 16);
    const uint32_t b_off  = (uint32_t)(((lane & 7) + ((lane >> 4) & 1) * 8) * ROW_B +
                                       ((lane >> 3) & 1) * 16);

    issue(0, 0);
    CP_COMMIT();

    const int NCH = NI / 64;
    for (int c = 0; c < NCH; c++) {
        if (c + 1 < NCH) { issue((c + 1) & 1, (c + 1) * 64); CP_COMMIT(); CP_WAIT(1); }
        else             { CP_WAIT(0); }
        __syncthreads();
        uint32_t base = sb + (c & 1) * STAGE_B;
#pragma unroll
        for (int kk = 0; kk < 4; kk++) {
            uint32_t ah0[4], al0[4], ah1[4], al1[4];
            LDSM4(ah0, base + OFF_AH + a_base + kk * 32);
            LDSM4(al0, base + OFF_AL + a_base + kk * 32);
            LDSM4(ah1, base + OFF_AH + a_base + 16 * ROW_B + kk * 32);
            LDSM4(al1, base + OFF_AL + a_base + 16 * ROW_B + kk * 32);
#pragma unroll
            for (int nt = 0; nt < 8; nt++) {
                uint32_t bh[4];
                uint32_t bo = b_off + nt * (16 * ROW_B) + kk * 32;
                LDSM4(bh, base + OFF_BH + bo);
                MMA16816(acc[0][2 * nt],     ah0, bh[0], bh[1]);
                MMA16816(acc[0][2 * nt],     al0, bh[0], bh[1]);
                MMA16816(acc[0][2 * nt + 1], ah0, bh[2], bh[3]);
                MMA16816(acc[0][2 * nt + 1], al0, bh[2], bh[3]);
                MMA16816(acc[1][2 * nt],     ah1, bh[0], bh[1]);
                MMA16816(acc[1][2 * nt],     al1, bh[0], bh[1]);
                MMA16816(acc[1][2 * nt + 1], ah1, bh[2], bh[3]);
                MMA16816(acc[1][2 * nt + 1], al1, bh[2], bh[3]);
            }
        }
        __syncthreads();
    }

    // epilogue: out[tok, n0+col] += w * acc
    const int cb = (lane & 3) * 2;
#pragma unroll
    for (int mf = 0; mf < 2; mf++) {
        int rbase = m0 + wid * 32 + mf * 16 + (lane >> 2);
#pragma unroll
        for (int half = 0; half < 2; half++) {
            int row = rbase + half * 8;
            if (row >= M) continue;
            int   tok = g_slot_token[start + row];
            float w   = g_slot_w[start + row];
            float* orow = out + (size_t)tok * NH + n0;
#pragma unroll
            for (int q = 0; q < 16; q++) {
                atomicAdd(orow + q * 8 + cb + 0, w * acc[mf][q][2 * half + 0]);
                atomicAdd(orow + q * 8 + cb + 1, w * acc[mf][q][2 * half + 1]);
            }
        }
    }
}

// ---------------- launch -----------------
extern "C" void kernel_launch(void* const* d_in, const int* in_sizes, int n_in,
                              void* d_out, int out_size) {
    const float* hidden = (const float*)d_in[0];   // [T, H]
    const void*  idx    = d_in[1];                 // [T, K] int32 or int64
    const float* wts    = (const float*)d_in[2];   // [T, K]
    const float* wgu    = (const float*)d_in[3];   // [E, 2I, H]
    const float* wdn    = (const float*)d_in[4];   // [E, H, I]
    (void)in_sizes; (void)n_in;

    cudaFuncSetAttribute(k_gemm1, cudaFuncAttributeMaxDynamicSharedMemorySize, SMEM_TOT);
    cudaFuncSetAttribute(k_gemm2, cudaFuncAttributeMaxDynamicSharedMemorySize, SMEM_TOT);

    // routing
    k_detect<<<1, 32>>>((const int*)idx);
    k_reset<<<1, 32>>>();
    k_count<<<(CAP + 255) / 256, 256>>>(idx);
    k_scan<<<1, 32>>>();
    k_scatter<<<(CAP + 255) / 256, 256>>>(idx, wts);

    // fp32 -> fp16 conversions
    k_cvt_hid<<<2048, 256>>>((const float4*)hidden);
    k_cvt_wgu<<<8192, 256>>>((const float4*)wgu);
    k_cvt_wdn<<<4096, 256>>>((const float4*)wdn);

    cudaMemsetAsync(d_out, 0, (size_t)out_size * sizeof(float), 0);

    // GEMM1: x = NI/64 = 22 tiles, y = worst-case M tiles (256 rows), z = experts
    dim3 g1(NI / 64, CAP / 256, NE);
    k_gemm1<<<g1, 256, SMEM_TOT>>>();

    // GEMM2: x = NH/128 = 16 tiles
    dim3 g2(NH / 128, CAP / 256, NE);
    k_gemm2<<<g2, 256, SMEM_TOT>>>((float*)d_out);
}

// round 9
// speedup vs baseline: 3.5878x; 1.5111x over previous
#include <cuda_runtime.h>
#include <cuda_fp16.h>
#include <cstdint>

// Problem constants
#define NE 16
#define NH 2048
#define NI 1408
#define NK 2
#define NT 8192
#define CAP (NT * NK)   // 16384 routed slots

// ---------------- scratch (device globals; no cudaMalloc allowed) ----------
__device__ int   g_counts[NE];
__device__ int   g_fill[NE];
__device__ int   g_offsets[NE + 1];
__device__ int   g_slot_token[CAP];
__device__ float g_slot_w[CAP];
__device__ int   g_is64;

// fp16 operands (round-to-nearest from fp32)
__device__ __align__(16) __half g_hid_h[(size_t)NT * NH];
__device__ __align__(16) __half g_wgu_h[(size_t)NE * 2 * NI * NH];
__device__ __align__(16) __half g_wdn_h[(size_t)NE * NH * NI];
__device__ __align__(16) __half g_h_h[(size_t)CAP * NI];

// ---------------- PTX helpers (baseline ISA only: sm_80+ features) ---------
__device__ __forceinline__ uint32_t smem_u32(const void* p) {
    uint32_t a;
    asm("{ .reg .u64 t; cvta.to.shared.u64 t, %1; cvt.u32.u64 %0, t; }" : "=r"(a) : "l"(p));
    return a;
}
#define CP_ASYNC16(dst, src) \
    asm volatile("cp.async.cg.shared.global [%0], [%1], 16;" :: "r"(dst), "l"(src))
#define CP_COMMIT() asm volatile("cp.async.commit_group;" ::: "memory")
#define CP_WAIT(N)  asm volatile("cp.async.wait_group %0;" :: "n"(N) : "memory")

#define LDSM4(r, addr) \
    asm volatile("ldmatrix.sync.aligned.m8n8.x4.shared.b16 {%0,%1,%2,%3}, [%4];" \
        : "=r"((r)[0]), "=r"((r)[1]), "=r"((r)[2]), "=r"((r)[3]) : "r"(addr))

#define MMA16816(c, a, b0_, b1_) \
    asm volatile("mma.sync.aligned.m16n8k16.row.col.f32.f16.f16.f32 " \
        "{%0,%1,%2,%3}, {%4,%5,%6,%7}, {%8,%9}, {%0,%1,%2,%3};" \
        : "+f"((c)[0]), "+f"((c)[1]), "+f"((c)[2]), "+f"((c)[3]) \
        : "r"((a)[0]), "r"((a)[1]), "r"((a)[2]), "r"((a)[3]), "r"(b0_), "r"(b1_))

// ---------------- dtype detection for top_k_index -----------------
__global__ void k_detect(const int* __restrict__ idx32) {
    if (threadIdx.x == 0) {
        int is64 = 1;
        for (int i = 0; i < 256; i++) {
            int lo = idx32[2 * i], hi = idx32[2 * i + 1];
            if (hi != 0 || lo < 0 || lo >= NE) { is64 = 0; break; }
        }
        g_is64 = is64;
    }
}
__device__ __forceinline__ int load_expert(const void* idx, int s) {
    if (g_is64) return (int)((const long long*)idx)[s];
    return ((const int*)idx)[s];
}

// ---------------- routing -----------------
__global__ void k_reset() {
    int i = threadIdx.x;
    if (i < NE) { g_counts[i] = 0; g_fill[i] = 0; }
}
__global__ void k_count(const void* __restrict__ idx) {
    int s = blockIdx.x * blockDim.x + threadIdx.x;
    if (s < CAP) {
        int e = load_expert(idx, s);
        if (e >= 0 && e < NE) atomicAdd(&g_counts[e], 1);
    }
}
__global__ void k_scan() {
    if (threadIdx.x == 0) {
        int acc = 0;
        for (int e = 0; e < NE; e++) { g_offsets[e] = acc; acc += g_counts[e]; }
        g_offsets[NE] = acc;
    }
}
__global__ void k_scatter(const void* __restrict__ idx, const float* __restrict__ w) {
    int s = blockIdx.x * blockDim.x + threadIdx.x;
    if (s < CAP) {
        int e = load_expert(idx, s);
        if (e >= 0 && e < NE) {
            int p = g_offsets[e] + atomicAdd(&g_fill[e], 1);
            g_slot_token[p] = s / NK;
            g_slot_w[p]     = w[s];
        }
    }
}

// ---------------- fp32 -> fp16 round conversions ----------------
__device__ __forceinline__ void cvt_round_body(const float4* __restrict__ s,
                                               __half2* __restrict__ hi, size_t n4) {
    size_t i = (size_t)blockIdx.x * blockDim.x + threadIdx.x;
    size_t stride = (size_t)gridDim.x * blockDim.x;
    for (; i < n4; i += stride) {
        float4 v = s[i];
        hi[2 * i]     = __halves2half2(__float2half(v.x), __float2half(v.y));
        hi[2 * i + 1] = __halves2half2(__float2half(v.z), __float2half(v.w));
    }
}
__global__ void k_cvt_hid(const float4* __restrict__ s) {
    cvt_round_body(s, (__half2*)g_hid_h, (size_t)NT * NH / 4);
}
__global__ void k_cvt_wgu(const float4* __restrict__ s) {
    cvt_round_body(s, (__half2*)g_wgu_h, (size_t)NE * 2 * NI * NH / 4);
}
__global__ void k_cvt_wdn(const float4* __restrict__ s) {
    cvt_round_body(s, (__half2*)g_wdn_h, (size_t)NE * NH * NI / 4);
}

// ---------------- HMMA GEMMs ----------------
// M-tile 256 x N-tile 128, K-chunks of 64.
// SMEM per stage: A (256 x 64 fp16) + B (128 x 64 fp16),
// row stride 72 elems (144 B; conflict-free ldmatrix), 2 stages.
#define ROW_B   144
#define A_TB    (256 * ROW_B)               // 36864 B
#define B_TB    (128 * ROW_B)               // 18432 B
#define STAGE_B (A_TB + B_TB)               // 55296 B
#define SMEM_TOT (2 * STAGE_B)              // 110592 B
#define OFF_A  0
#define OFF_B  A_TB

// Warp layout: 8 warps, warp w owns rows [w*32, w*32+32) (2 m16 frags), all 128 N.
// Per k16 step: 2 A LDSM + 8 B LDSM, 32 MMAs.

// ---- GEMM1: C[256 slots, 64 gate | 64 up], K = NH, 32 chunks of 64 ----
__global__ __launch_bounds__(256, 1) void k_gemm1() {
    extern __shared__ char smem[];
    const int e     = blockIdx.z;
    const int start = g_offsets[e];
    const int M     = g_offsets[e + 1] - start;
    const int m0    = blockIdx.y * 256;
    if (m0 >= M) return;
    const int i0 = blockIdx.x * 64;     // gridDim.x = NI/64 = 22

    const int tid  = threadIdx.x;
    const int wid  = tid >> 5;
    const int lane = tid & 31;
    uint32_t sb = smem_u32(smem);

    const int vrow = tid >> 3;          // 0..31
    const int col8 = tid & 7;
    size_t arow[8], brow[4];
#pragma unroll
    for (int i = 0; i < 8; i++) {
        int row = vrow + 32 * i;        // 0..255
        int ar  = m0 + row; if (ar >= M) ar = M - 1;
        arow[i] = (size_t)g_slot_token[start + ar] * NH;
    }
#pragma unroll
    for (int i = 0; i < 4; i++) {
        int rb = vrow + 32 * i;         // 0..127
        int wr = (rb < 64) ? (i0 + rb) : (NI + i0 + rb - 64);
        brow[i] = (size_t)e * (2 * NI) * NH + (size_t)wr * NH;
    }

    auto issue = [&](int s, int kk) {
        uint32_t base = sb + s * STAGE_B;
#pragma unroll
        for (int i = 0; i < 8; i++) {
            int row = vrow + 32 * i;
            uint32_t d = base + row * ROW_B + col8 * 16;
            CP_ASYNC16(d + OFF_A, g_hid_h + arow[i] + kk + col8 * 8);
        }
#pragma unroll
        for (int i = 0; i < 4; i++) {
            int rb = vrow + 32 * i;
            uint32_t d = base + rb * ROW_B + col8 * 16;
            CP_ASYNC16(d + OFF_B, g_wgu_h + brow[i] + kk + col8 * 8);
        }
    };

    float acc[2][16][4];
#pragma unroll
    for (int mf = 0; mf < 2; mf++)
#pragma unroll
        for (int q = 0; q < 16; q++)
#pragma unroll
            for (int i = 0; i < 4; i++) acc[mf][q][i] = 0.f;

    const uint32_t a_base = (uint32_t)((wid * 32 + (lane & 15)) * ROW_B + (lane >> 4) * 16);
    const uint32_t b_off  = (uint32_t)(((lane & 7) + ((lane >> 4) & 1) * 8) * ROW_B +
                                       ((lane >> 3) & 1) * 16);

    issue(0, 0);
    CP_COMMIT();

    const int NCH = NH / 64;
    for (int c = 0; c < NCH; c++) {
        if (c + 1 < NCH) { issue((c + 1) & 1, (c + 1) * 64); CP_COMMIT(); CP_WAIT(1); }
        else             { CP_WAIT(0); }
        __syncthreads();
        uint32_t base = sb + (c & 1) * STAGE_B;
#pragma unroll
        for (int kk = 0; kk < 4; kk++) {
            uint32_t ah0[4], ah1[4];
            LDSM4(ah0, base + OFF_A + a_base + kk * 32);
            LDSM4(ah1, base + OFF_A + a_base + 16 * ROW_B + kk * 32);
#pragma unroll
            for (int nt = 0; nt < 8; nt++) {
                uint32_t bh[4];
                uint32_t bo = b_off + nt * (16 * ROW_B) + kk * 32;
                LDSM4(bh, base + OFF_B + bo);
                MMA16816(acc[0][2 * nt],     ah0, bh[0], bh[1]);
                MMA16816(acc[0][2 * nt + 1], ah0, bh[2], bh[3]);
                MMA16816(acc[1][2 * nt],     ah1, bh[0], bh[1]);
                MMA16816(acc[1][2 * nt + 1], ah1, bh[2], bh[3]);
            }
        }
        __syncthreads();
    }

    // epilogue: cols 0..63 = gate(i0+j), 64..127 = up(i0+j); h = silu(g)*u
    const int cb = (lane & 3) * 2;
#pragma unroll
    for (int mf = 0; mf < 2; mf++) {
        int rbase = m0 + wid * 32 + mf * 16 + (lane >> 2);
#pragma unroll
        for (int q = 0; q < 8; q++) {
            int col = i0 + q * 8 + cb;
#pragma unroll
            for (int half = 0; half < 2; half++) {
                int row = rbase + half * 8;
                if (row >= M) continue;
                float g0 = acc[mf][q][2 * half + 0],     g1 = acc[mf][q][2 * half + 1];
                float u0 = acc[mf][q + 8][2 * half + 0], u1 = acc[mf][q + 8][2 * half + 1];
                float h0 = u0 * g0 / (1.f + __expf(-g0));
                float h1 = u1 * g1 / (1.f + __expf(-g1));
                size_t o = (size_t)(start + row) * NI + col;
                *(__half2*)(g_h_h + o) =
                    __halves2half2(__float2half(h0), __float2half(h1));
            }
        }
    }
}

// ---- GEMM2: C[256 slots, 128 hidden], K = NI, 22 chunks of 64; scatter-add ----
__global__ __launch_bounds__(256, 1) void k_gemm2(float* __restrict__ out) {
    extern __shared__ char smem[];
    const int e     = blockIdx.z;
    const int start = g_offsets[e];
    const int M     = g_offsets[e + 1] - start;
    const int m0    = blockIdx.y * 256;
    if (m0 >= M) return;
    const int n0 = blockIdx.x * 128;    // gridDim.x = NH/128 = 16

    const int tid  = threadIdx.x;
    const int wid  = tid >> 5;
    const int lane = tid & 31;
    uint32_t sb = smem_u32(smem);

    const int vrow = tid >> 3;
    const int col8 = tid & 7;
    size_t arow[8], brow[4];
#pragma unroll
    for (int i = 0; i < 8; i++) {
        int row = vrow + 32 * i;
        int ar  = m0 + row; if (ar >= M) ar = M - 1;
        arow[i] = (size_t)(start + ar) * NI;
    }
#pragma unroll
    for (int i = 0; i < 4; i++) {
        int rb = vrow + 32 * i;
        brow[i] = (size_t)e * NH * NI + (size_t)(n0 + rb) * NI;
    }

    auto issue = [&](int s, int kk) {
        uint32_t base = sb + s * STAGE_B;
#pragma unroll
        for (int i = 0; i < 8; i++) {
            int row = vrow + 32 * i;
            uint32_t d = base + row * ROW_B + col8 * 16;
            CP_ASYNC16(d + OFF_A, g_h_h + arow[i] + kk + col8 * 8);
        }
#pragma unroll
        for (int i = 0; i < 4; i++) {
            int rb = vrow + 32 * i;
            uint32_t d = base + rb * ROW_B + col8 * 16;
            CP_ASYNC16(d + OFF_B, g_wdn_h + brow[i] + kk + col8 * 8);
        }
    };

    float acc[2][16][4];
#pragma unroll
    for (int mf = 0; mf < 2; mf++)
#pragma unroll
        for (int q = 0; q < 16; q++)
#pragma unroll
            for (int i = 0; i < 4; i++) acc[mf][q][i] = 0.f;

    const uint32_t a_base = (uint32_t)((wid * 32 + (lane & 15)) * ROW_B + (lane >> 4) * 16);
    const uint32_t b_off  = (uint32_t)(((lane & 7) + ((lane >> 4) & 1) * 8) * ROW_B +
                                       ((lane >> 3) & 1) * 16);

    issue(0, 0);
    CP_COMMIT();

    const int NCH = NI / 64;
    for (int c = 0; c < NCH; c++) {
        if (c + 1 < NCH) { issue((c + 1) & 1, (c + 1) * 64); CP_COMMIT(); CP_WAIT(1); }
        else             { CP_WAIT(0); }
        __syncthreads();
        uint32_t base = sb + (c & 1) * STAGE_B;
#pragma unroll
        for (int kk = 0; kk < 4; kk++) {
            uint32_t ah0[4], ah1[4];
            LDSM4(ah0, base + OFF_A + a_base + kk * 32);
            LDSM4(ah1, base + OFF_A + a_base + 16 * ROW_B + kk * 32);
#pragma unroll
            for (int nt = 0; nt < 8; nt++) {
                uint32_t bh[4];
                uint32_t bo = b_off + nt * (16 * ROW_B) + kk * 32;
                LDSM4(bh, base + OFF_B + bo);
                MMA16816(acc[0][2 * nt],     ah0, bh[0], bh[1]);
                MMA16816(acc[0][2 * nt + 1], ah0, bh[2], bh[3]);
                MMA16816(acc[1][2 * nt],     ah1, bh[0], bh[1]);
                MMA16816(acc[1][2 * nt + 1], ah1, bh[2], bh[3]);
            }
        }
        __syncthreads();
    }

    // epilogue: out[tok, n0+col] += w * acc
    const int cb = (lane & 3) * 2;
#pragma unroll
    for (int mf = 0; mf < 2; mf++) {
        int rbase = m0 + wid * 32 + mf * 16 + (lane >> 2);
#pragma unroll
        for (int half = 0; half < 2; half++) {
            int row = rbase + half * 8;
            if (row >= M) continue;
            int   tok = g_slot_token[start + row];
            float w   = g_slot_w[start + row];
            float* orow = out + (size_t)tok * NH + n0;
#pragma unroll
            for (int q = 0; q < 16; q++) {
                atomicAdd(orow + q * 8 + cb + 0, w * acc[mf][q][2 * half + 0]);
                atomicAdd(orow + q * 8 + cb + 1, w * acc[mf][q][2 * half + 1]);
            }
        }
    }
}

// ---------------- launch -----------------
extern "C" void kernel_launch(void* const* d_in, const int* in_sizes, int n_in,
                              void* d_out, int out_size) {
    const float* hidden = (const float*)d_in[0];   // [T, H]
    const void*  idx    = d_in[1];                 // [T, K] int32 or int64
    const float* wts    = (const float*)d_in[2];   // [T, K]
    const float* wgu    = (const float*)d_in[3];   // [E, 2I, H]
    const float* wdn    = (const float*)d_in[4];   // [E, H, I]
    (void)in_sizes; (void)n_in;

    cudaFuncSetAttribute(k_gemm1, cudaFuncAttributeMaxDynamicSharedMemorySize, SMEM_TOT);
    cudaFuncSetAttribute(k_gemm2, cudaFuncAttributeMaxDynamicSharedMemorySize, SMEM_TOT);

    // routing
    k_detect<<<1, 32>>>((const int*)idx);
    k_reset<<<1, 32>>>();
    k_count<<<(CAP + 255) / 256, 256>>>(idx);
    k_scan<<<1, 32>>>();
    k_scatter<<<(CAP + 255) / 256, 256>>>(idx, wts);

    // fp32 -> fp16 conversions
    k_cvt_hid<<<2048, 256>>>((const float4*)hidden);
    k_cvt_wgu<<<8192, 256>>>((const float4*)wgu);
    k_cvt_wdn<<<4096, 256>>>((const float4*)wdn);

    cudaMemsetAsync(d_out, 0, (size_t)out_size * sizeof(float), 0);

    // GEMM1: x = NI/64 = 22 tiles, y = worst-case M tiles (256 rows), z = experts
    dim3 g1(NI / 64, CAP / 256, NE);
    k_gemm1<<<g1, 256, SMEM_TOT>>>();

    // GEMM2: x = NH/128 = 16 tiles
    dim3 g2(NH / 128, CAP / 256, NE);
    k_gemm2<<<g2, 256, SMEM_TOT>>>((float*)d_out);
}

// round 10
// speedup vs baseline: 4.6283x; 1.2900x over previous
#include <cuda_runtime.h>
#include <cuda_fp16.h>
#include <cstdint>

// Problem constants
#define NE 16
#define NH 2048
#define NI 1408
#define NK 2
#define NT 8192
#define CAP (NT * NK)   // 16384 routed slots

// ---------------- scratch (device globals; no cudaMalloc allowed) ----------
__device__ int   g_counts[NE];
__device__ int   g_fill[NE];
__device__ int   g_offsets[NE + 1];
__device__ int   g_slot_token[CAP];
__device__ float g_slot_w[CAP];
__device__ int   g_is64;

// fp16 operands (round-to-nearest from fp32)
__device__ __align__(16) __half g_hid_h[(size_t)NT * NH];
__device__ __align__(16) __half g_wgu_h[(size_t)NE * 2 * NI * NH];
__device__ __align__(16) __half g_wdn_h[(size_t)NE * NH * NI];
__device__ __align__(16) __half g_h_h[(size_t)CAP * NI];

// ---------------- PTX helpers (baseline ISA only: sm_80+ features) ---------
__device__ __forceinline__ uint32_t smem_u32(const void* p) {
    uint32_t a;
    asm("{ .reg .u64 t; cvta.to.shared.u64 t, %1; cvt.u32.u64 %0, t; }" : "=r"(a) : "l"(p));
    return a;
}
#define CP_ASYNC16(dst, src) \
    asm volatile("cp.async.cg.shared.global [%0], [%1], 16;" :: "r"(dst), "l"(src))
#define CP_COMMIT() asm volatile("cp.async.commit_group;" ::: "memory")
#define CP_WAIT(N)  asm volatile("cp.async.wait_group %0;" :: "n"(N) : "memory")

#define LDSM4(r, addr) \
    asm volatile("ldmatrix.sync.aligned.m8n8.x4.shared.b16 {%0,%1,%2,%3}, [%4];" \
        : "=r"((r)[0]), "=r"((r)[1]), "=r"((r)[2]), "=r"((r)[3]) : "r"(addr))

#define MMA16816(c, a, b0_, b1_) \
    asm volatile("mma.sync.aligned.m16n8k16.row.col.f32.f16.f16.f32 " \
        "{%0,%1,%2,%3}, {%4,%5,%6,%7}, {%8,%9}, {%0,%1,%2,%3};" \
        : "+f"((c)[0]), "+f"((c)[1]), "+f"((c)[2]), "+f"((c)[3]) \
        : "r"((a)[0]), "r"((a)[1]), "r"((a)[2]), "r"((a)[3]), "r"(b0_), "r"(b1_))

// ---------------- dtype detection for top_k_index -----------------
__global__ void k_detect(const int* __restrict__ idx32) {
    if (threadIdx.x == 0) {
        int is64 = 1;
        for (int i = 0; i < 256; i++) {
            int lo = idx32[2 * i], hi = idx32[2 * i + 1];
            if (hi != 0 || lo < 0 || lo >= NE) { is64 = 0; break; }
        }
        g_is64 = is64;
    }
}
__device__ __forceinline__ int load_expert(const void* idx, int s) {
    if (g_is64) return (int)((const long long*)idx)[s];
    return ((const int*)idx)[s];
}

// ---------------- routing -----------------
__global__ void k_reset() {
    int i = threadIdx.x;
    if (i < NE) { g_counts[i] = 0; g_fill[i] = 0; }
}
__global__ void k_count(const void* __restrict__ idx) {
    int s = blockIdx.x * blockDim.x + threadIdx.x;
    if (s < CAP) {
        int e = load_expert(idx, s);
        if (e >= 0 && e < NE) atomicAdd(&g_counts[e], 1);
    }
}
__global__ void k_scan() {
    if (threadIdx.x == 0) {
        int acc = 0;
        for (int e = 0; e < NE; e++) { g_offsets[e] = acc; acc += g_counts[e]; }
        g_offsets[NE] = acc;
    }
}
__global__ void k_scatter(const void* __restrict__ idx, const float* __restrict__ w) {
    int s = blockIdx.x * blockDim.x + threadIdx.x;
    if (s < CAP) {
        int e = load_expert(idx, s);
        if (e >= 0 && e < NE) {
            int p = g_offsets[e] + atomicAdd(&g_fill[e], 1);
            g_slot_token[p] = s / NK;
            g_slot_w[p]     = w[s];
        }
    }
}

// ---------------- fp32 -> fp16 round conversions ----------------
__device__ __forceinline__ void cvt_round_body(const float4* __restrict__ s,
                                               __half2* __restrict__ hi, size_t n4) {
    size_t i = (size_t)blockIdx.x * blockDim.x + threadIdx.x;
    size_t stride = (size_t)gridDim.x * blockDim.x;
    for (; i < n4; i += stride) {
        float4 v = s[i];
        hi[2 * i]     = __halves2half2(__float2half(v.x), __float2half(v.y));
        hi[2 * i + 1] = __halves2half2(__float2half(v.z), __float2half(v.w));
    }
}
__global__ void k_cvt_hid(const float4* __restrict__ s) {
    cvt_round_body(s, (__half2*)g_hid_h, (size_t)NT * NH / 4);
}
__global__ void k_cvt_wgu(const float4* __restrict__ s) {
    cvt_round_body(s, (__half2*)g_wgu_h, (size_t)NE * 2 * NI * NH / 4);
}
__global__ void k_cvt_wdn(const float4* __restrict__ s) {
    cvt_round_body(s, (__half2*)g_wdn_h, (size_t)NE * NH * NI / 4);
}

// ---------------- HMMA GEMMs ----------------
// M-tile 128 x N-tile 128, K-chunks of 64, 2 CTAs/SM.
// Warps in 4x2 grid: warp tile 32 rows x 64 cols.
// SMEM per stage: A (128 x 64 fp16) + B (128 x 64 fp16), row stride 144 B.
#define ROW_B   144
#define A_TB    (128 * ROW_B)               // 18432 B
#define B_TB    (128 * ROW_B)               // 18432 B
#define STAGE_B (A_TB + B_TB)               // 36864 B
#define SMEM_TOT (2 * STAGE_B)              // 73728 B
#define OFF_A  0
#define OFF_B  A_TB

// ---- GEMM1: C[128 slots, 64 channels as gate|up pairs], K = NH ----
// B tile row rb: half = rb>>6 selects channel group (32 ch per warp half),
// local = rb&63: (local&31) = channel-in-group, (local>>5) = 0 gate / 1 up.
__global__ __launch_bounds__(256, 2) void k_gemm1() {
    extern __shared__ char smem[];
    const int e     = blockIdx.z;
    const int start = g_offsets[e];
    const int M     = g_offsets[e + 1] - start;
    const int m0    = blockIdx.y * 128;
    if (m0 >= M) return;
    const int i0 = blockIdx.x * 64;     // gridDim.x = NI/64 = 22

    const int tid    = threadIdx.x;
    const int wid    = tid >> 5;
    const int lane   = tid & 31;
    const int warp_m = wid >> 1;        // 0..3
    const int warp_n = wid & 1;         // 0..1
    uint32_t sb = smem_u32(smem);

    const int vrow = tid >> 3;          // 0..31
    const int col8 = tid & 7;
    size_t arow[4], brow[4];
#pragma unroll
    for (int i = 0; i < 4; i++) {
        int row = vrow + 32 * i;        // 0..127
        int ar  = m0 + row; if (ar >= M) ar = M - 1;
        arow[i] = (size_t)g_slot_token[start + ar] * NH;
        int rb    = row;
        int half_ = rb >> 6;
        int local = rb & 63;
        int ch    = i0 + half_ * 32 + (local & 31);
        int role  = (local >> 5) & 1;
        brow[i] = (size_t)e * (2 * NI) * NH + (size_t)(ch + role * NI) * NH;
    }

    auto issue = [&](int s, int kk) {
        uint32_t base = sb + s * STAGE_B;
#pragma unroll
        for (int i = 0; i < 4; i++) {
            int row = vrow + 32 * i;
            uint32_t d = base + row * ROW_B + col8 * 16;
            CP_ASYNC16(d + OFF_A, g_hid_h + arow[i] + kk + col8 * 8);
            CP_ASYNC16(d + OFF_B, g_wgu_h + brow[i] + kk + col8 * 8);
        }
    };

    float acc[2][8][4];
#pragma unroll
    for (int mf = 0; mf < 2; mf++)
#pragma unroll
        for (int q = 0; q < 8; q++)
#pragma unroll
            for (int i = 0; i < 4; i++) acc[mf][q][i] = 0.f;

    const uint32_t a_base = (uint32_t)((warp_m * 32 + (lane & 15)) * ROW_B + (lane >> 4) * 16);
    const uint32_t b_base = (uint32_t)((warp_n * 64 + (lane & 7) + ((lane >> 4) & 1) * 8) * ROW_B +
                                       ((lane >> 3) & 1) * 16);

    issue(0, 0);
    CP_COMMIT();

    const int NCH = NH / 64;
    for (int c = 0; c < NCH; c++) {
        if (c + 1 < NCH) { issue((c + 1) & 1, (c + 1) * 64); CP_COMMIT(); CP_WAIT(1); }
        else             { CP_WAIT(0); }
        __syncthreads();
        uint32_t base = sb + (c & 1) * STAGE_B;
#pragma unroll
        for (int kk = 0; kk < 4; kk++) {
            uint32_t a0[4], a1[4];
            LDSM4(a0, base + OFF_A + a_base + kk * 32);
            LDSM4(a1, base + OFF_A + a_base + 16 * ROW_B + kk * 32);
#pragma unroll
            for (int nt = 0; nt < 4; nt++) {
                uint32_t bh[4];
                uint32_t bo = b_base + nt * (16 * ROW_B) + kk * 32;
                LDSM4(bh, base + OFF_B + bo);
                MMA16816(acc[0][2 * nt],     a0, bh[0], bh[1]);
                MMA16816(acc[0][2 * nt + 1], a0, bh[2], bh[3]);
                MMA16816(acc[1][2 * nt],     a1, bh[0], bh[1]);
                MMA16816(acc[1][2 * nt + 1], a1, bh[2], bh[3]);
            }
        }
        __syncthreads();
    }

    // epilogue: acc[.][q] (q<4) = gate of channel i0+warp_n*32+q*8+cb,
    //           acc[.][q+4]     = up   of same channel; h = silu(g)*u
    const int cb = (lane & 3) * 2;
#pragma unroll
    for (int mf = 0; mf < 2; mf++) {
        int rbase = m0 + warp_m * 32 + mf * 16 + (lane >> 2);
#pragma unroll
        for (int q = 0; q < 4; q++) {
            int ch = i0 + warp_n * 32 + q * 8 + cb;
#pragma unroll
            for (int half = 0; half < 2; half++) {
                int row = rbase + half * 8;
                if (row >= M) continue;
                float g0 = acc[mf][q][2 * half + 0],     g1 = acc[mf][q][2 * half + 1];
                float u0 = acc[mf][q + 4][2 * half + 0], u1 = acc[mf][q + 4][2 * half + 1];
                float h0 = u0 * g0 / (1.f + __expf(-g0));
                float h1 = u1 * g1 / (1.f + __expf(-g1));
                size_t o = (size_t)(start + row) * NI + ch;
                *(__half2*)(g_h_h + o) =
                    __halves2half2(__float2half(h0), __float2half(h1));
            }
        }
    }
}

// ---- GEMM2: C[128 slots, 128 hidden], K = NI; weighted atomic scatter ----
__global__ __launch_bounds__(256, 2) void k_gemm2(float* __restrict__ out) {
    extern __shared__ char smem[];
    const int e     = blockIdx.z;
    const int start = g_offsets[e];
    const int M     = g_offsets[e + 1] - start;
    const int m0    = blockIdx.y * 128;
    if (m0 >= M) return;
    const int n0 = blockIdx.x * 128;    // gridDim.x = NH/128 = 16

    const int tid    = threadIdx.x;
    const int wid    = tid >> 5;
    const int lane   = tid & 31;
    const int warp_m = wid >> 1;
    const int warp_n = wid & 1;
    uint32_t sb = smem_u32(smem);

    const int vrow = tid >> 3;
    const int col8 = tid & 7;
    size_t arow[4], brow[4];
#pragma unroll
    for (int i = 0; i < 4; i++) {
        int row = vrow + 32 * i;
        int ar  = m0 + row; if (ar >= M) ar = M - 1;
        arow[i] = (size_t)(start + ar) * NI;
        brow[i] = (size_t)e * NH * NI + (size_t)(n0 + row) * NI;
    }

    auto issue = [&](int s, int kk) {
        uint32_t base = sb + s * STAGE_B;
#pragma unroll
        for (int i = 0; i < 4; i++) {
            int row = vrow + 32 * i;
            uint32_t d = base + row * ROW_B + col8 * 16;
            CP_ASYNC16(d + OFF_A, g_h_h   + arow[i] + kk + col8 * 8);
            CP_ASYNC16(d + OFF_B, g_wdn_h + brow[i] + kk + col8 * 8);
        }
    };

    float acc[2][8][4];
#pragma unroll
    for (int mf = 0; mf < 2; mf++)
#pragma unroll
        for (int q = 0; q < 8; q++)
#pragma unroll
            for (int i = 0; i < 4; i++) acc[mf][q][i] = 0.f;

    const uint32_t a_base = (uint32_t)((warp_m * 32 + (lane & 15)) * ROW_B + (lane >> 4) * 16);
    const uint32_t b_base = (uint32_t)((warp_n * 64 + (lane & 7) + ((lane >> 4) & 1) * 8) * ROW_B +
                                       ((lane >> 3) & 1) * 16);

    issue(0, 0);
    CP_COMMIT();

    const int NCH = NI / 64;
    for (int c = 0; c < NCH; c++) {
        if (c + 1 < NCH) { issue((c + 1) & 1, (c + 1) * 64); CP_COMMIT(); CP_WAIT(1); }
        else             { CP_WAIT(0); }
        __syncthreads();
        uint32_t base = sb + (c & 1) * STAGE_B;
#pragma unroll
        for (int kk = 0; kk < 4; kk++) {
            uint32_t a0[4], a1[4];
            LDSM4(a0, base + OFF_A + a_base + kk * 32);
            LDSM4(a1, base + OFF_A + a_base + 16 * ROW_B + kk * 32);
#pragma unroll
            for (int nt = 0; nt < 4; nt++) {
                uint32_t bh[4];
                uint32_t bo = b_base + nt * (16 * ROW_B) + kk * 32;
                LDSM4(bh, base + OFF_B + bo);
                MMA16816(acc[0][2 * nt],     a0, bh[0], bh[1]);
                MMA16816(acc[0][2 * nt + 1], a0, bh[2], bh[3]);
                MMA16816(acc[1][2 * nt],     a1, bh[0], bh[1]);
                MMA16816(acc[1][2 * nt + 1], a1, bh[2], bh[3]);
            }
        }
        __syncthreads();
    }

    // epilogue: out[tok, n0 + warp_n*64 + col] += w * acc
    const int cb = (lane & 3) * 2;
#pragma unroll
    for (int mf = 0; mf < 2; mf++) {
        int rbase = m0 + warp_m * 32 + mf * 16 + (lane >> 2);
#pragma unroll
        for (int half = 0; half < 2; half++) {
            int row = rbase + half * 8;
            if (row >= M) continue;
            int   tok = g_slot_token[start + row];
            float w   = g_slot_w[start + row];
            float* orow = out + (size_t)tok * NH + n0 + warp_n * 64;
#pragma unroll
            for (int q = 0; q < 8; q++) {
                atomicAdd(orow + q * 8 + cb + 0, w * acc[mf][q][2 * half + 0]);
                atomicAdd(orow + q * 8 + cb + 1, w * acc[mf][q][2 * half + 1]);
            }
        }
    }
}

// ---------------- launch -----------------
extern "C" void kernel_launch(void* const* d_in, const int* in_sizes, int n_in,
                              void* d_out, int out_size) {
    const float* hidden = (const float*)d_in[0];   // [T, H]
    const void*  idx    = d_in[1];                 // [T, K] int32 or int64
    const float* wts    = (const float*)d_in[2];   // [T, K]
    const float* wgu    = (const float*)d_in[3];   // [E, 2I, H]
    const float* wdn    = (const float*)d_in[4];   // [E, H, I]
    (void)in_sizes; (void)n_in;

    cudaFuncSetAttribute(k_gemm1, cudaFuncAttributeMaxDynamicSharedMemorySize, SMEM_TOT);
    cudaFuncSetAttribute(k_gemm2, cudaFuncAttributeMaxDynamicSharedMemorySize, SMEM_TOT);

    // routing
    k_detect<<<1, 32>>>((const int*)idx);
    k_reset<<<1, 32>>>();
    k_count<<<(CAP + 255) / 256, 256>>>(idx);
    k_scan<<<1, 32>>>();
    k_scatter<<<(CAP + 255) / 256, 256>>>(idx, wts);

    // fp32 -> fp16 conversions
    k_cvt_hid<<<2048, 256>>>((const float4*)hidden);
    k_cvt_wgu<<<8192, 256>>>((const float4*)wgu);
    k_cvt_wdn<<<4096, 256>>>((const float4*)wdn);

    cudaMemsetAsync(d_out, 0, (size_t)out_size * sizeof(float), 0);

    // GEMM1: x = NI/64 = 22 tiles, y = worst-case M tiles (128 rows), z = experts
    dim3 g1(NI / 64, CAP / 128, NE);
    k_gemm1<<<g1, 256, SMEM_TOT>>>();

    // GEMM2: x = NH/128 = 16 tiles
    dim3 g2(NH / 128, CAP / 128, NE);
    k_gemm2<<<g2, 256, SMEM_TOT>>>((float*)d_out);
}

// round 11
// speedup vs baseline: 4.9835x; 1.0768x over previous
#include <cuda_runtime.h>
#include <cuda_fp16.h>
#include <cstdint>

// Problem constants
#define NE 16
#define NH 2048
#define NI 1408
#define NK 2
#define NT 8192
#define CAP (NT * NK)   // 16384 routed slots

// ---------------- scratch (device globals; no cudaMalloc allowed) ----------
__device__ int   g_offsets[NE + 1];
__device__ int   g_slot_token[CAP];
__device__ float g_slot_w[CAP];

// fp16 operands (round-to-nearest from fp32)
__device__ __align__(16) __half g_hid_h[(size_t)NT * NH];
__device__ __align__(16) __half g_wgu_h[(size_t)NE * 2 * NI * NH];
__device__ __align__(16) __half g_wdn_h[(size_t)NE * NH * NI];
__device__ __align__(16) __half g_h_h[(size_t)CAP * NI];

// ---------------- PTX helpers (baseline ISA only: sm_80+ features) ---------
__device__ __forceinline__ uint32_t smem_u32(const void* p) {
    uint32_t a;
    asm("{ .reg .u64 t; cvta.to.shared.u64 t, %1; cvt.u32.u64 %0, t; }" : "=r"(a) : "l"(p));
    return a;
}
#define CP_ASYNC16(dst, src) \
    asm volatile("cp.async.cg.shared.global [%0], [%1], 16;" :: "r"(dst), "l"(src))
#define CP_COMMIT() asm volatile("cp.async.commit_group;" ::: "memory")
#define CP_WAIT(N)  asm volatile("cp.async.wait_group %0;" :: "n"(N) : "memory")

#define LDSM4(r, addr) \
    asm volatile("ldmatrix.sync.aligned.m8n8.x4.shared.b16 {%0,%1,%2,%3}, [%4];" \
        : "=r"((r)[0]), "=r"((r)[1]), "=r"((r)[2]), "=r"((r)[3]) : "r"(addr))

#define MMA16816(c, a, b0_, b1_) \
    asm volatile("mma.sync.aligned.m16n8k16.row.col.f32.f16.f16.f32 " \
        "{%0,%1,%2,%3}, {%4,%5,%6,%7}, {%8,%9}, {%0,%1,%2,%3};" \
        : "+f"((c)[0]), "+f"((c)[1]), "+f"((c)[2]), "+f"((c)[3]) \
        : "r"((a)[0]), "r"((a)[1]), "r"((a)[2]), "r"((a)[3]), "r"(b0_), "r"(b1_))

// ---------------- fused routing: detect + count + scan + scatter ----------
__global__ void k_route(const int* __restrict__ idx32, const float* __restrict__ w) {
    __shared__ int cnt[NE], base_[NE], fill[NE];
    __shared__ int is64_s;
    const int tid = threadIdx.x;
    if (tid < NE) { cnt[tid] = 0; fill[tid] = 0; }
    if (tid == 0) is64_s = 1;
    __syncthreads();
    // dtype detect: JAX x64-off silently downgrades int64->int32.
    // 256 consecutive pairs of (v in [0,16), 0) => int64. In-bounds either way.
    if (tid < 256) {
        int lo = idx32[2 * tid], hi = idx32[2 * tid + 1];
        if (hi != 0 || lo < 0 || lo >= NE) atomicExch(&is64_s, 0);
    }
    __syncthreads();
    const int is64 = is64_s;
    for (int s = tid; s < CAP; s += blockDim.x) {
        int e = is64 ? (int)((const long long*)idx32)[s] : idx32[s];
        if (e >= 0 && e < NE) atomicAdd(&cnt[e], 1);
    }
    __syncthreads();
    if (tid == 0) {
        int acc = 0;
        for (int e = 0; e < NE; e++) { base_[e] = acc; g_offsets[e] = acc; acc += cnt[e]; }
        g_offsets[NE] = acc;
    }
    __syncthreads();
    for (int s = tid; s < CAP; s += blockDim.x) {
        int e = is64 ? (int)((const long long*)idx32)[s] : idx32[s];
        if (e >= 0 && e < NE) {
            int p = base_[e] + atomicAdd(&fill[e], 1);
            g_slot_token[p] = s / NK;
            g_slot_w[p]     = w[s];
        }
    }
}

// ---------------- fp32 -> fp16 round conversions ----------------
__device__ __forceinline__ void cvt_round_body(const float4* __restrict__ s,
                                               __half2* __restrict__ hi, size_t n4) {
    size_t i = (size_t)blockIdx.x * blockDim.x + threadIdx.x;
    size_t stride = (size_t)gridDim.x * blockDim.x;
    for (; i < n4; i += stride) {
        float4 v = s[i];
        hi[2 * i]     = __halves2half2(__float2half(v.x), __float2half(v.y));
        hi[2 * i + 1] = __halves2half2(__float2half(v.z), __float2half(v.w));
    }
}
__global__ void k_cvt_hid(const float4* __restrict__ s) {
    cvt_round_body(s, (__half2*)g_hid_h, (size_t)NT * NH / 4);
}
__global__ void k_cvt_wgu(const float4* __restrict__ s) {
    cvt_round_body(s, (__half2*)g_wgu_h, (size_t)NE * 2 * NI * NH / 4);
}
__global__ void k_cvt_wdn(const float4* __restrict__ s) {
    cvt_round_body(s, (__half2*)g_wdn_h, (size_t)NE * NH * NI / 4);
}

// ---------------- HMMA GEMMs ----------------
// M-tile 128 x N-tile 128, K-chunks of 64, 2 CTAs/SM, 3-stage cp.async
// pipeline with a single __syncthreads per chunk.
// Warps in 4x2 grid: warp tile 32 rows x 64 cols.
// SMEM per stage: A (128 x 64 fp16) + B (128 x 64 fp16), row stride 144 B.
#define ROW_B   144
#define A_TB    (128 * ROW_B)               // 18432 B
#define B_TB    (128 * ROW_B)               // 18432 B
#define STAGE_B (A_TB + B_TB)               // 36864 B
#define NSTAGE  3
#define SMEM_TOT (NSTAGE * STAGE_B)         // 110592 B
#define OFF_A  0
#define OFF_B  A_TB

// ---- GEMM1: C[128 slots, 64 channels as gate|up pairs], K = NH ----
__global__ __launch_bounds__(256, 2) void k_gemm1() {
    extern __shared__ char smem[];
    const int e     = blockIdx.z;
    const int start = g_offsets[e];
    const int M     = g_offsets[e + 1] - start;
    const int m0    = blockIdx.y * 128;
    if (m0 >= M) return;
    const int i0 = blockIdx.x * 64;     // gridDim.x = NI/64 = 22

    const int tid    = threadIdx.x;
    const int wid    = tid >> 5;
    const int lane   = tid & 31;
    const int warp_m = wid >> 1;        // 0..3
    const int warp_n = wid & 1;         // 0..1
    uint32_t sb = smem_u32(smem);

    const int vrow = tid >> 3;          // 0..31
    const int col8 = tid & 7;
    size_t arow[4], brow[4];
#pragma unroll
    for (int i = 0; i < 4; i++) {
        int row = vrow + 32 * i;        // 0..127
        int ar  = m0 + row; if (ar >= M) ar = M - 1;
        arow[i] = (size_t)g_slot_token[start + ar] * NH;
        int half_ = row >> 6;
        int local = row & 63;
        int ch    = i0 + half_ * 32 + (local & 31);
        int role  = (local >> 5) & 1;
        brow[i] = (size_t)e * (2 * NI) * NH + (size_t)(ch + role * NI) * NH;
    }

    auto issue = [&](int s, int kk) {
        uint32_t base = sb + s * STAGE_B;
#pragma unroll
        for (int i = 0; i < 4; i++) {
            int row = vrow + 32 * i;
            uint32_t d = base + row * ROW_B + col8 * 16;
            CP_ASYNC16(d + OFF_A, g_hid_h + arow[i] + kk + col8 * 8);
            CP_ASYNC16(d + OFF_B, g_wgu_h + brow[i] + kk + col8 * 8);
        }
    };

    float acc[2][8][4];
#pragma unroll
    for (int mf = 0; mf < 2; mf++)
#pragma unroll
        for (int q = 0; q < 8; q++)
#pragma unroll
            for (int i = 0; i < 4; i++) acc[mf][q][i] = 0.f;

    const uint32_t a_base = (uint32_t)((warp_m * 32 + (lane & 15)) * ROW_B + (lane >> 4) * 16);
    const uint32_t b_base = (uint32_t)((warp_n * 64 + (lane & 7) + ((lane >> 4) & 1) * 8) * ROW_B +
                                       ((lane >> 3) & 1) * 16);

    issue(0, 0);   CP_COMMIT();
    issue(1, 64);  CP_COMMIT();

    const int NCH = NH / 64;
    for (int c = 0; c < NCH; c++) {
        if (c + 1 < NCH) CP_WAIT(1); else CP_WAIT(0);
        __syncthreads();
        uint32_t base = sb + (c % NSTAGE) * STAGE_B;
#pragma unroll
        for (int kk = 0; kk < 4; kk++) {
            uint32_t a0[4], a1[4];
            LDSM4(a0, base + OFF_A + a_base + kk * 32);
            LDSM4(a1, base + OFF_A + a_base + 16 * ROW_B + kk * 32);
#pragma unroll
            for (int nt = 0; nt < 4; nt++) {
                uint32_t bh[4];
                uint32_t bo = b_base + nt * (16 * ROW_B) + kk * 32;
                LDSM4(bh, base + OFF_B + bo);
                MMA16816(acc[0][2 * nt],     a0, bh[0], bh[1]);
                MMA16816(acc[0][2 * nt + 1], a0, bh[2], bh[3]);
                MMA16816(acc[1][2 * nt],     a1, bh[0], bh[1]);
                MMA16816(acc[1][2 * nt + 1], a1, bh[2], bh[3]);
            }
        }
        if (c + 2 < NCH) { issue((c + 2) % NSTAGE, (c + 2) * 64); CP_COMMIT(); }
    }

    // epilogue: acc[.][q] (q<4) = gate, acc[.][q+4] = up; h = silu(g)*u
    const int cb = (lane & 3) * 2;
#pragma unroll
    for (int mf = 0; mf < 2; mf++) {
        int rbase = m0 + warp_m * 32 + mf * 16 + (lane >> 2);
#pragma unroll
        for (int q = 0; q < 4; q++) {
            int ch = i0 + warp_n * 32 + q * 8 + cb;
#pragma unroll
            for (int half = 0; half < 2; half++) {
                int row = rbase + half * 8;
                if (row >= M) continue;
                float g0 = acc[mf][q][2 * half + 0],     g1 = acc[mf][q][2 * half + 1];
                float u0 = acc[mf][q + 4][2 * half + 0], u1 = acc[mf][q + 4][2 * half + 1];
                float h0 = u0 * g0 / (1.f + __expf(-g0));
                float h1 = u1 * g1 / (1.f + __expf(-g1));
                size_t o = (size_t)(start + row) * NI + ch;
                *(__half2*)(g_h_h + o) =
                    __halves2half2(__float2half(h0), __float2half(h1));
            }
        }
    }
}

// ---- GEMM2: C[128 slots, 128 hidden], K = NI; weighted atomic scatter ----
__global__ __launch_bounds__(256, 2) void k_gemm2(float* __restrict__ out) {
    extern __shared__ char smem[];
    const int e     = blockIdx.z;
    const int start = g_offsets[e];
    const int M     = g_offsets[e + 1] - start;
    const int m0    = blockIdx.y * 128;
    if (m0 >= M) return;
    const int n0 = blockIdx.x * 128;    // gridDim.x = NH/128 = 16

    const int tid    = threadIdx.x;
    const int wid    = tid >> 5;
    const int lane   = tid & 31;
    const int warp_m = wid >> 1;
    const int warp_n = wid & 1;
    uint32_t sb = smem_u32(smem);

    const int vrow = tid >> 3;
    const int col8 = tid & 7;
    size_t arow[4], brow[4];
#pragma unroll
    for (int i = 0; i < 4; i++) {
        int row = vrow + 32 * i;
        int ar  = m0 + row; if (ar >= M) ar = M - 1;
        arow[i] = (size_t)(start + ar) * NI;
        brow[i] = (size_t)e * NH * NI + (size_t)(n0 + row) * NI;
    }

    auto issue = [&](int s, int kk) {
        uint32_t base = sb + s * STAGE_B;
#pragma unroll
        for (int i = 0; i < 4; i++) {
            int row = vrow + 32 * i;
            uint32_t d = base + row * ROW_B + col8 * 16;
            CP_ASYNC16(d + OFF_A, g_h_h   + arow[i] + kk + col8 * 8);
            CP_ASYNC16(d + OFF_B, g_wdn_h + brow[i] + kk + col8 * 8);
        }
    };

    float acc[2][8][4];
#pragma unroll
    for (int mf = 0; mf < 2; mf++)
#pragma unroll
        for (int q = 0; q < 8; q++)
#pragma unroll
            for (int i = 0; i < 4; i++) acc[mf][q][i] = 0.f;

    const uint32_t a_base = (uint32_t)((warp_m * 32 + (lane & 15)) * ROW_B + (lane >> 4) * 16);
    const uint32_t b_base = (uint32_t)((warp_n * 64 + (lane & 7) + ((lane >> 4) & 1) * 8) * ROW_B +
                                       ((lane >> 3) & 1) * 16);

    issue(0, 0);   CP_COMMIT();
    issue(1, 64);  CP_COMMIT();

    const int NCH = NI / 64;
    for (int c = 0; c < NCH; c++) {
        if (c + 1 < NCH) CP_WAIT(1); else CP_WAIT(0);
        __syncthreads();
        uint32_t base = sb + (c % NSTAGE) * STAGE_B;
#pragma unroll
        for (int kk = 0; kk < 4; kk++) {
            uint32_t a0[4], a1[4];
            LDSM4(a0, base + OFF_A + a_base + kk * 32);
            LDSM4(a1, base + OFF_A + a_base + 16 * ROW_B + kk * 32);
#pragma unroll
            for (int nt = 0; nt < 4; nt++) {
                uint32_t bh[4];
                uint32_t bo = b_base + nt * (16 * ROW_B) + kk * 32;
                LDSM4(bh, base + OFF_B + bo);
                MMA16816(acc[0][2 * nt],     a0, bh[0], bh[1]);
                MMA16816(acc[0][2 * nt + 1], a0, bh[2], bh[3]);
                MMA16816(acc[1][2 * nt],     a1, bh[0], bh[1]);
                MMA16816(acc[1][2 * nt + 1], a1, bh[2], bh[3]);
            }
        }
        if (c + 2 < NCH) { issue((c + 2) % NSTAGE, (c + 2) * 64); CP_COMMIT(); }
    }

    // epilogue: out[tok, n0 + warp_n*64 + col] += w * acc
    const int cb = (lane & 3) * 2;
#pragma unroll
    for (int mf = 0; mf < 2; mf++) {
        int rbase = m0 + warp_m * 32 + mf * 16 + (lane >> 2);
#pragma unroll
        for (int half = 0; half < 2; half++) {
            int row = rbase + half * 8;
            if (row >= M) continue;
            int   tok = g_slot_token[start + row];
            float w   = g_slot_w[start + row];
            float* orow = out + (size_t)tok * NH + n0 + warp_n * 64;
#pragma unroll
            for (int q = 0; q < 8; q++) {
                atomicAdd(orow + q * 8 + cb + 0, w * acc[mf][q][2 * half + 0]);
                atomicAdd(orow + q * 8 + cb + 1, w * acc[mf][q][2 * half + 1]);
            }
        }
    }
}

// ---------------- launch -----------------
extern "C" void kernel_launch(void* const* d_in, const int* in_sizes, int n_in,
                              void* d_out, int out_size) {
    const float* hidden = (const float*)d_in[0];   // [T, H]
    const void*  idx    = d_in[1];                 // [T, K] int32 or int64
    const float* wts    = (const float*)d_in[2];   // [T, K]
    const float* wgu    = (const float*)d_in[3];   // [E, 2I, H]
    const float* wdn    = (const float*)d_in[4];   // [E, H, I]
    (void)in_sizes; (void)n_in;

    cudaFuncSetAttribute(k_gemm1, cudaFuncAttributeMaxDynamicSharedMemorySize, SMEM_TOT);
    cudaFuncSetAttribute(k_gemm2, cudaFuncAttributeMaxDynamicSharedMemorySize, SMEM_TOT);

    // fused routing
    k_route<<<1, 1024>>>((const int*)idx, wts);

    // fp32 -> fp16 conversions
    k_cvt_hid<<<2048, 256>>>((const float4*)hidden);
    k_cvt_wgu<<<8192, 256>>>((const float4*)wgu);
    k_cvt_wdn<<<4096, 256>>>((const float4*)wdn);

    cudaMemsetAsync(d_out, 0, (size_t)out_size * sizeof(float), 0);

    // GEMM1: x = NI/64 = 22 tiles, y = worst-case M tiles (128 rows), z = experts
    dim3 g1(NI / 64, CAP / 128, NE);
    k_gemm1<<<g1, 256, SMEM_TOT>>>();

    // GEMM2: x = NH/128 = 16 tiles
    dim3 g2(NH / 128, CAP / 128, NE);
    k_gemm2<<<g2, 256, SMEM_TOT>>>((float*)d_out);
}